// round 5
// baseline (speedup 1.0000x reference)
#include <cuda_runtime.h>
#include <cuda_bf16.h>
#include <math.h>
#include <stdint.h>

#define KK 3
#define NN 16384
#define MM 4096
#define DD 128
#define HH 64
#define KS 192   // split reduction dim: 3 x 64 bf16

// Scratch (device globals: allocation-free rule)
// fx = mma-A side (n rows): [hi, hi, lo]; fz = mma-B side (m rows): [hi, lo, hi]
// dot = hi*hi + hi*lo + lo*hi
__device__ __nv_bfloat16 g_fxh[KK * NN * KS];
__device__ __nv_bfloat16 g_fzh[KK * MM * KS];
__device__ float g_sn[KK * NN];
__device__ float g_sm[KK * MM];

__device__ __forceinline__ float sp(float v) {
    return fmaxf(v, 0.0f) + log1pf(__expf(-fabsf(v)));
}

// ======================= async / mma helpers (sm_80 PTX only) =======================
__device__ __forceinline__ uint32_t smem_u32_of(const void* p) {
    return (uint32_t)__cvta_generic_to_shared(p);
}
__device__ __forceinline__ void cp16(uint32_t dst, const void* src) {
    asm volatile("cp.async.cg.shared.global [%0], [%1], 16;" :: "r"(dst), "l"(src));
}
__device__ __forceinline__ void cp_commit() {
    asm volatile("cp.async.commit_group;" ::: "memory");
}
template <int N_>
__device__ __forceinline__ void cp_wait() {
    asm volatile("cp.async.wait_group %0;" :: "n"(N_) : "memory");
}
__device__ __forceinline__ void ldsm4(uint32_t* f, uint32_t addr) {
    asm volatile("ldmatrix.sync.aligned.m8n8.x4.shared.b16 {%0,%1,%2,%3}, [%4];"
                 : "=r"(f[0]), "=r"(f[1]), "=r"(f[2]), "=r"(f[3]) : "r"(addr));
}
__device__ __forceinline__ void mma_bf16(float* c, const uint32_t* a, uint32_t b0, uint32_t b1) {
    asm volatile(
        "mma.sync.aligned.m16n8k16.row.col.f32.bf16.bf16.f32 "
        "{%0,%1,%2,%3}, {%4,%5,%6,%7}, {%8,%9}, {%0,%1,%2,%3};"
        : "+f"(c[0]), "+f"(c[1]), "+f"(c[2]), "+f"(c[3])
        : "r"(a[0]), "r"(a[1]), "r"(a[2]), "r"(a[3]), "r"(b0), "r"(b1));
}

// =====================================================================
// Kernel A: phi MLP -> bf16 hi/lo split features + fp32 norms (unchanged)
// =====================================================================
__global__ __launch_bounds__(256) void phi_kernel(
    const float* __restrict__ x, const float* __restrict__ z,
    const float* __restrict__ W1, const float* __restrict__ b1,
    const float* __restrict__ W2, const float* __restrict__ b2,
    const float* __restrict__ W3, const float* __restrict__ b3) {
    extern __shared__ float smem[];
    float* XT  = smem;           // [128][64]
    float* W1T = smem + 8192;    // [128][64]
    float* W2T = smem + 16384;   // [64][64]
    float* W3T = smem + 20480;   // [64][64]
    float* H1T = smem + 24576;   // [64][64]
    float* RED = smem + 28672;   // [64][16]

    const int t  = threadIdx.x;
    const int tx = t & 15, ty = t >> 4;
    const int k  = blockIdx.y;
    const int bx = blockIdx.x;
    const bool isx = (bx < NN / 64);
    const int r0 = (isx ? bx : bx - NN / 64) * 64;
    const float* src = isx ? x : z;
    __nv_bfloat16* dsth = isx ? (g_fxh + (size_t)k * NN * KS)
                              : (g_fzh + (size_t)k * MM * KS);
    float* sdst = isx ? (g_sn + k * NN) : (g_sm + k * MM);

    const float* W1k = W1 + k * HH * DD;
    for (int q = t; q < HH * DD / 4; q += 256) {
        int h = q >> 5, d4 = (q & 31) << 2;
        float4 v = *(const float4*)(W1k + h * DD + d4);
        W1T[(d4 + 0) * 64 + h] = v.x; W1T[(d4 + 1) * 64 + h] = v.y;
        W1T[(d4 + 2) * 64 + h] = v.z; W1T[(d4 + 3) * 64 + h] = v.w;
    }
    const float* W2k = W2 + k * HH * HH;
    const float* W3k = W3 + k * HH * HH;
    for (int q = t; q < HH * HH / 4; q += 256) {
        int g = q >> 4, h4 = (q & 15) << 2;
        float4 v2 = *(const float4*)(W2k + g * HH + h4);
        W2T[(h4 + 0) * 64 + g] = v2.x; W2T[(h4 + 1) * 64 + g] = v2.y;
        W2T[(h4 + 2) * 64 + g] = v2.z; W2T[(h4 + 3) * 64 + g] = v2.w;
        float4 v3 = *(const float4*)(W3k + g * HH + h4);
        W3T[(h4 + 0) * 64 + g] = v3.x; W3T[(h4 + 1) * 64 + g] = v3.y;
        W3T[(h4 + 2) * 64 + g] = v3.z; W3T[(h4 + 3) * 64 + g] = v3.w;
    }
    for (int q = t; q < 64 * DD / 4; q += 256) {
        int r = q >> 5, d4 = (q & 31) << 2;
        float4 v = *(const float4*)(src + (size_t)(r0 + r) * DD + d4);
        XT[(d4 + 0) * 64 + r] = v.x; XT[(d4 + 1) * 64 + r] = v.y;
        XT[(d4 + 2) * 64 + r] = v.z; XT[(d4 + 3) * 64 + r] = v.w;
    }
    __syncthreads();

    float acc[4][4];
    #pragma unroll
    for (int i = 0; i < 4; i++)
        #pragma unroll
        for (int j = 0; j < 4; j++) acc[i][j] = 0.0f;

    #pragma unroll 4
    for (int d = 0; d < DD; ++d) {
        float4 a4 = *(const float4*)&XT[d * 64 + (ty << 2)];
        float4 b4 = *(const float4*)&W1T[d * 64 + (tx << 2)];
        float av[4] = {a4.x, a4.y, a4.z, a4.w};
        float bv[4] = {b4.x, b4.y, b4.z, b4.w};
        #pragma unroll
        for (int i = 0; i < 4; i++)
            #pragma unroll
            for (int j = 0; j < 4; j++)
                acc[i][j] = fmaf(av[i], bv[j], acc[i][j]);
    }
    {
        const float* b1k = b1 + k * HH;
        #pragma unroll
        for (int j = 0; j < 4; j++) {
            float bj = b1k[(tx << 2) + j];
            #pragma unroll
            for (int i = 0; i < 4; i++)
                H1T[((tx << 2) + j) * 64 + (ty << 2) + i] = sp(acc[i][j] + bj);
        }
    }
    __syncthreads();

    #pragma unroll
    for (int i = 0; i < 4; i++)
        #pragma unroll
        for (int j = 0; j < 4; j++) acc[i][j] = 0.0f;
    #pragma unroll 4
    for (int h = 0; h < HH; ++h) {
        float4 a4 = *(const float4*)&H1T[h * 64 + (ty << 2)];
        float4 b4 = *(const float4*)&W2T[h * 64 + (tx << 2)];
        float av[4] = {a4.x, a4.y, a4.z, a4.w};
        float bv[4] = {b4.x, b4.y, b4.z, b4.w};
        #pragma unroll
        for (int i = 0; i < 4; i++)
            #pragma unroll
            for (int j = 0; j < 4; j++)
                acc[i][j] = fmaf(av[i], bv[j], acc[i][j]);
    }
    __syncthreads();
    {
        const float* b2k = b2 + k * HH;
        #pragma unroll
        for (int j = 0; j < 4; j++) {
            float bj = b2k[(tx << 2) + j];
            #pragma unroll
            for (int i = 0; i < 4; i++)
                H1T[((tx << 2) + j) * 64 + (ty << 2) + i] = sp(acc[i][j] + bj);
        }
    }
    __syncthreads();

    #pragma unroll
    for (int i = 0; i < 4; i++)
        #pragma unroll
        for (int j = 0; j < 4; j++) acc[i][j] = 0.0f;
    #pragma unroll 4
    for (int g = 0; g < HH; ++g) {
        float4 a4 = *(const float4*)&H1T[g * 64 + (ty << 2)];
        float4 b4 = *(const float4*)&W3T[g * 64 + (tx << 2)];
        float av[4] = {a4.x, a4.y, a4.z, a4.w};
        float bv[4] = {b4.x, b4.y, b4.z, b4.w};
        #pragma unroll
        for (int i = 0; i < 4; i++)
            #pragma unroll
            for (int j = 0; j < 4; j++)
                acc[i][j] = fmaf(av[i], bv[j], acc[i][j]);
    }
    {
        const float* b3k = b3 + k * HH;
        #pragma unroll
        for (int i = 0; i < 4; i++) {
            int row = r0 + (ty << 2) + i;
            float fv[4];
            #pragma unroll
            for (int j = 0; j < 4; j++) fv[j] = acc[i][j] + b3k[(tx << 2) + j];

            __nv_bfloat16 h[4], l[4];
            #pragma unroll
            for (int j = 0; j < 4; j++) {
                h[j] = __float2bfloat16(fv[j]);
                l[j] = __float2bfloat16(fv[j] - __bfloat162float(h[j]));
            }
            __nv_bfloat162 hp0 = __halves2bfloat162(h[0], h[1]);
            __nv_bfloat162 hp1 = __halves2bfloat162(h[2], h[3]);
            __nv_bfloat162 lp0 = __halves2bfloat162(l[0], l[1]);
            __nv_bfloat162 lp1 = __halves2bfloat162(l[2], l[3]);

            __nv_bfloat16* rowp = dsth + (size_t)row * KS + (tx << 2);
            *(__nv_bfloat162*)(rowp + 0) = hp0;
            *(__nv_bfloat162*)(rowp + 2) = hp1;
            if (isx) {  // A side (fx): [hi, hi, lo]
                *(__nv_bfloat162*)(rowp + 64)  = hp0;
                *(__nv_bfloat162*)(rowp + 66)  = hp1;
                *(__nv_bfloat162*)(rowp + 128) = lp0;
                *(__nv_bfloat162*)(rowp + 130) = lp1;
            } else {    // B side (fz): [hi, lo, hi]
                *(__nv_bfloat162*)(rowp + 64)  = lp0;
                *(__nv_bfloat162*)(rowp + 66)  = lp1;
                *(__nv_bfloat162*)(rowp + 128) = hp0;
                *(__nv_bfloat162*)(rowp + 130) = hp1;
            }
            RED[((ty << 2) + i) * 16 + tx] =
                fv[0] * fv[0] + fv[1] * fv[1] + fv[2] * fv[2] + fv[3] * fv[3];
        }
    }
    __syncthreads();
    if (t < 64) {
        float s = 0.0f;
        #pragma unroll
        for (int q = 0; q < 16; q++) s += RED[t * 16 + q];
        sdst[r0 + t] = s;
    }
}

// =====================================================================
// Kernel B: mma.sync bf16 pairwise GEMM + fused RBF epilogue.
// CTA: 256 threads (8 warps), tile 128n x 64m, warp tile 32n x 32m.
// K pipelined in 64-element chunks (9 total), 4-stage cp.async ring.
// 2 CTAs/SM (smem ~100KB, regs <=128 via launch_bounds(256,2)).
// =====================================================================
#define NT 128
#define MT 64
#define NSTG 4
#define A_STB (128 * 128)        // 16384: 128 n-rows x 64 bf16
#define B_STB (64 * 128)         // 8192:  64 m-rows x 64 bf16
#define STG_B (A_STB + B_STB)    // 24576
#define OFF_SN2 0                // 3*128 f32
#define OFF_SM2 1536             // 3*64 f32
#define OFF_ST2 2304
#define SMEM_TOT2 (OFF_ST2 + NSTG * STG_B)   // 100608

// load one 64-k chunk: A 128 rows (1024 cp16), B 64 rows (512 cp16); 256 thr
__device__ __forceinline__ void load_chunk(int c, int n0, int m0,
                                           uint32_t stage, int t) {
    int k = c / 3, kc = c % 3;
    const __nv_bfloat16* gA = g_fxh + ((size_t)k * NN + n0) * KS + kc * 64;
    const __nv_bfloat16* gB = g_fzh + ((size_t)k * MM + m0) * KS + kc * 64;
    #pragma unroll
    for (int i = 0; i < 4; i++) {
        int q = t + i * 256;
        int r = q >> 3, cc = q & 7;
        cp16(stage + r * 128 + (uint32_t)((cc ^ (r & 7)) << 4),
             (const char*)(gA + (size_t)r * KS) + cc * 16);
    }
    #pragma unroll
    for (int i = 0; i < 2; i++) {
        int q = t + i * 256;
        int r = q >> 3, cc = q & 7;
        cp16(stage + A_STB + r * 128 + (uint32_t)((cc ^ (r & 7)) << 4),
             (const char*)(gB + (size_t)r * KS) + cc * 16);
    }
}

__global__ __launch_bounds__(256, 2) void pair_kernel(
    const float* __restrict__ log_sigma, const float* __restrict__ kw,
    float* __restrict__ out) {
    extern __shared__ char sm8[];
    const uint32_t sb = smem_u32_of(sm8);
    float* snS = (float*)(sm8 + OFF_SN2);
    float* smS = (float*)(sm8 + OFF_SM2);

    const int t = threadIdx.x;
    const int w = t >> 5, lane = t & 31;
    const int quad = lane >> 2, qid = lane & 3;
    const int wn = w & 3, wm = w >> 2;       // 4 over n, 2 over m
    const int nb = wn * 32, mb = wm * 32;
    const int m0 = blockIdx.x * MT;
    const int n0 = blockIdx.y * NT;

    for (int q = t; q < 3 * 128; q += 256)
        snS[q] = g_sn[(q >> 7) * NN + n0 + (q & 127)];
    for (int q = t; q < 3 * 64; q += 256)
        smS[q] = g_sm[(q >> 6) * MM + m0 + (q & 63)];

    float w0r = kw[0], w1r = kw[1], w2r = kw[2];
    float wmax = fmaxf(fmaxf(w0r, w1r), w2r);
    float ew0 = __expf(w0r - wmax), ew1 = __expf(w1r - wmax), ew2 = __expf(w2r - wmax);
    float winv = 1.0f / (ew0 + ew1 + ew2);
    float wkv[3] = {ew0 * winv, ew1 * winv, ew2 * winv};
    float c1[3];
    #pragma unroll
    for (int k = 0; k < 3; k++)
        c1[k] = 0.5f * exp2f(-log_sigma[k] * 3.3219280948873623f);

    // prologue: fill all 4 stages (chunks 0..3)
    #pragma unroll
    for (int c = 0; c < 4; c++) {
        load_chunk(c, n0, m0, sb + OFF_ST2 + c * STG_B, t);
        cp_commit();
    }

    float res[2][4][4];
    #pragma unroll
    for (int mi = 0; mi < 2; mi++)
        #pragma unroll
        for (int nj = 0; nj < 4; nj++)
            #pragma unroll
            for (int r = 0; r < 4; r++) res[mi][nj][r] = 0.0f;

    float acc[2][4][4];

    // ldmatrix per-lane bases
    const int a_row = nb + (lane & 15);
    const int a_cb  = lane >> 4;
    const int b_row = mb + ((lane >> 4) << 3) + (lane & 7);
    const int b_cb  = (lane >> 3) & 1;

    for (int c = 0; c < 9; c++) {
        cp_wait<NSTG - 1>();
        __syncthreads();

        if (c % 3 == 0) {
            #pragma unroll
            for (int mi = 0; mi < 2; mi++)
                #pragma unroll
                for (int nj = 0; nj < 4; nj++)
                    #pragma unroll
                    for (int r = 0; r < 4; r++) acc[mi][nj][r] = 0.0f;
        }

        const uint32_t a_base = sb + OFF_ST2 + (uint32_t)(c & 3) * STG_B;
        const uint32_t b_base = a_base + A_STB;

        #pragma unroll
        for (int ks = 0; ks < 4; ks++) {
            uint32_t af[2][4];
            #pragma unroll
            for (int mi = 0; mi < 2; mi++) {
                int row = a_row + mi * 16;
                int cc = (2 * ks + a_cb) ^ (row & 7);
                ldsm4(af[mi], a_base + row * 128 + (cc << 4));
            }
            uint32_t bf[2][4];
            #pragma unroll
            for (int nj2 = 0; nj2 < 2; nj2++) {
                int row = b_row + nj2 * 16;
                int cc = (2 * ks + b_cb) ^ (row & 7);
                ldsm4(bf[nj2], b_base + row * 128 + (cc << 4));
            }
            #pragma unroll
            for (int mi = 0; mi < 2; mi++)
                #pragma unroll
                for (int nj2 = 0; nj2 < 2; nj2++) {
                    mma_bf16(acc[mi][2 * nj2 + 0], af[mi], bf[nj2][0], bf[nj2][1]);
                    mma_bf16(acc[mi][2 * nj2 + 1], af[mi], bf[nj2][2], bf[nj2][3]);
                }
        }

        if (c % 3 == 2) {
            int k = c / 3;
            float c1k = c1[k], c2k = 2.0f * c1k, wkk = wkv[k];
            float pn[2][2];
            #pragma unroll
            for (int mi = 0; mi < 2; mi++) {
                pn[mi][0] = c1k * snS[k * 128 + nb + mi * 16 + quad];
                pn[mi][1] = c1k * snS[k * 128 + nb + mi * 16 + quad + 8];
            }
            #pragma unroll
            for (int nj = 0; nj < 4; nj++) {
                float2 pm2 = *(float2*)&smS[k * 64 + mb + nj * 8 + 2 * qid];
                float pm0 = c1k * pm2.x, pm1 = c1k * pm2.y;
                #pragma unroll
                for (int mi = 0; mi < 2; mi++) {
                    float g0 = fminf(fmaf(c2k, acc[mi][nj][0], -(pn[mi][0] + pm0)), 0.0f);
                    float g1 = fminf(fmaf(c2k, acc[mi][nj][1], -(pn[mi][0] + pm1)), 0.0f);
                    float g2 = fminf(fmaf(c2k, acc[mi][nj][2], -(pn[mi][1] + pm0)), 0.0f);
                    float g3 = fminf(fmaf(c2k, acc[mi][nj][3], -(pn[mi][1] + pm1)), 0.0f);
                    res[mi][nj][0] = fmaf(wkk, __expf(g0), res[mi][nj][0]);
                    res[mi][nj][1] = fmaf(wkk, __expf(g1), res[mi][nj][1]);
                    res[mi][nj][2] = fmaf(wkk, __expf(g2), res[mi][nj][2]);
                    res[mi][nj][3] = fmaf(wkk, __expf(g3), res[mi][nj][3]);
                }
            }
        }

        __syncthreads();   // all reads of stage (c&3) done
        if (c + 4 < 9) {
            load_chunk(c + 4, n0, m0, sb + OFF_ST2 + (uint32_t)((c + 4) & 3) * STG_B, t);
            cp_commit();
        } else {
            cp_commit();   // empty group keeps wait_group accounting exact
        }
    }

    // store: rows = n, cols = m (contiguous float2 along m)
    #pragma unroll
    for (int mi = 0; mi < 2; mi++) {
        int nrow = n0 + nb + mi * 16 + quad;
        #pragma unroll
        for (int nj = 0; nj < 4; nj++) {
            float* p0 = out + (size_t)nrow * MM + m0 + mb + nj * 8 + 2 * qid;
            *(float2*)p0 = make_float2(res[mi][nj][0], res[mi][nj][1]);
            float* p1 = p0 + (size_t)8 * MM;
            *(float2*)p1 = make_float2(res[mi][nj][2], res[mi][nj][3]);
        }
    }
}

extern "C" void kernel_launch(void* const* d_in, const int* in_sizes, int n_in,
                              void* d_out, int out_size) {
    const float* x  = (const float*)d_in[0];
    const float* z  = (const float*)d_in[1];
    const float* W1 = (const float*)d_in[2];
    const float* b1 = (const float*)d_in[3];
    const float* W2 = (const float*)d_in[4];
    const float* b2 = (const float*)d_in[5];
    const float* W3 = (const float*)d_in[6];
    const float* b3 = (const float*)d_in[7];
    const float* ls = (const float*)d_in[8];
    const float* kwp = (const float*)d_in[9];
    float* out = (float*)d_out;

    cudaFuncSetAttribute(phi_kernel, cudaFuncAttributeMaxDynamicSharedMemorySize, 29696 * 4);
    cudaFuncSetAttribute(pair_kernel, cudaFuncAttributeMaxDynamicSharedMemorySize, SMEM_TOT2);

    phi_kernel<<<dim3(320, 3), 256, 29696 * 4>>>(x, z, W1, b1, W2, b2, W3, b3);
    pair_kernel<<<dim3(MM / MT, NN / NT), 256, SMEM_TOT2>>>(ls, kwp, out);
}

// round 6
// speedup vs baseline: 1.6036x; 1.6036x over previous
#include <cuda_runtime.h>
#include <cuda_bf16.h>
#include <math.h>
#include <stdint.h>

#define KK 3
#define NN 16384
#define MM 4096
#define DD 128
#define HH 64
#define KS 192   // split reduction dim: 3 x 64 bf16

// Scratch (device globals: allocation-free rule)
// fx = mma-A side (n rows): [hi, hi, lo]; fz = mma-B side (m rows): [hi, lo, hi]
// dot = hi*hi + hi*lo + lo*hi
__device__ __nv_bfloat16 g_fxh[KK * NN * KS];
__device__ __nv_bfloat16 g_fzh[KK * MM * KS];
__device__ float g_sn[KK * NN];
__device__ float g_sm[KK * MM];

__device__ __forceinline__ float sp(float v) {
    return fmaxf(v, 0.0f) + log1pf(__expf(-fabsf(v)));
}

// ======================= async / mma helpers (sm_80 PTX only) =======================
__device__ __forceinline__ uint32_t smem_u32_of(const void* p) {
    return (uint32_t)__cvta_generic_to_shared(p);
}
__device__ __forceinline__ void cp16(uint32_t dst, const void* src) {
    asm volatile("cp.async.cg.shared.global [%0], [%1], 16;" :: "r"(dst), "l"(src));
}
__device__ __forceinline__ void cp_commit() {
    asm volatile("cp.async.commit_group;" ::: "memory");
}
template <int N_>
__device__ __forceinline__ void cp_wait() {
    asm volatile("cp.async.wait_group %0;" :: "n"(N_) : "memory");
}
__device__ __forceinline__ void ldsm4(uint32_t* f, uint32_t addr) {
    asm volatile("ldmatrix.sync.aligned.m8n8.x4.shared.b16 {%0,%1,%2,%3}, [%4];"
                 : "=r"(f[0]), "=r"(f[1]), "=r"(f[2]), "=r"(f[3]) : "r"(addr));
}
__device__ __forceinline__ void mma_bf16(float* c, const uint32_t* a, uint32_t b0, uint32_t b1) {
    asm volatile(
        "mma.sync.aligned.m16n8k16.row.col.f32.bf16.bf16.f32 "
        "{%0,%1,%2,%3}, {%4,%5,%6,%7}, {%8,%9}, {%0,%1,%2,%3};"
        : "+f"(c[0]), "+f"(c[1]), "+f"(c[2]), "+f"(c[3])
        : "r"(a[0]), "r"(a[1]), "r"(a[2]), "r"(a[3]), "r"(b0), "r"(b1));
}

// =====================================================================
// Kernel A: phi MLP -> bf16 hi/lo split features + fp32 norms.
// RED aliases W1T (only live during GEMM1) -> smem 114688 B -> 2 CTAs/SM.
// =====================================================================
__global__ __launch_bounds__(256, 2) void phi_kernel(
    const float* __restrict__ x, const float* __restrict__ z,
    const float* __restrict__ W1, const float* __restrict__ b1,
    const float* __restrict__ W2, const float* __restrict__ b2,
    const float* __restrict__ W3, const float* __restrict__ b3) {
    extern __shared__ float smem[];
    float* XT  = smem;           // [128][64]
    float* W1T = smem + 8192;    // [128][64]
    float* W2T = smem + 16384;   // [64][64]
    float* W3T = smem + 20480;   // [64][64]
    float* H1T = smem + 24576;   // [64][64]
    float* RED = W1T;            // alias: [64][16], used after GEMM3 only

    const int t  = threadIdx.x;
    const int tx = t & 15, ty = t >> 4;
    const int k  = blockIdx.y;
    const int bx = blockIdx.x;
    const bool isx = (bx < NN / 64);
    const int r0 = (isx ? bx : bx - NN / 64) * 64;
    const float* src = isx ? x : z;
    __nv_bfloat16* dsth = isx ? (g_fxh + (size_t)k * NN * KS)
                              : (g_fzh + (size_t)k * MM * KS);
    float* sdst = isx ? (g_sn + k * NN) : (g_sm + k * MM);

    const float* W1k = W1 + k * HH * DD;
    for (int q = t; q < HH * DD / 4; q += 256) {
        int h = q >> 5, d4 = (q & 31) << 2;
        float4 v = *(const float4*)(W1k + h * DD + d4);
        W1T[(d4 + 0) * 64 + h] = v.x; W1T[(d4 + 1) * 64 + h] = v.y;
        W1T[(d4 + 2) * 64 + h] = v.z; W1T[(d4 + 3) * 64 + h] = v.w;
    }
    const float* W2k = W2 + k * HH * HH;
    const float* W3k = W3 + k * HH * HH;
    for (int q = t; q < HH * HH / 4; q += 256) {
        int g = q >> 4, h4 = (q & 15) << 2;
        float4 v2 = *(const float4*)(W2k + g * HH + h4);
        W2T[(h4 + 0) * 64 + g] = v2.x; W2T[(h4 + 1) * 64 + g] = v2.y;
        W2T[(h4 + 2) * 64 + g] = v2.z; W2T[(h4 + 3) * 64 + g] = v2.w;
        float4 v3 = *(const float4*)(W3k + g * HH + h4);
        W3T[(h4 + 0) * 64 + g] = v3.x; W3T[(h4 + 1) * 64 + g] = v3.y;
        W3T[(h4 + 2) * 64 + g] = v3.z; W3T[(h4 + 3) * 64 + g] = v3.w;
    }
    for (int q = t; q < 64 * DD / 4; q += 256) {
        int r = q >> 5, d4 = (q & 31) << 2;
        float4 v = *(const float4*)(src + (size_t)(r0 + r) * DD + d4);
        XT[(d4 + 0) * 64 + r] = v.x; XT[(d4 + 1) * 64 + r] = v.y;
        XT[(d4 + 2) * 64 + r] = v.z; XT[(d4 + 3) * 64 + r] = v.w;
    }
    __syncthreads();

    float acc[4][4];
    #pragma unroll
    for (int i = 0; i < 4; i++)
        #pragma unroll
        for (int j = 0; j < 4; j++) acc[i][j] = 0.0f;

    #pragma unroll 4
    for (int d = 0; d < DD; ++d) {
        float4 a4 = *(const float4*)&XT[d * 64 + (ty << 2)];
        float4 b4 = *(const float4*)&W1T[d * 64 + (tx << 2)];
        float av[4] = {a4.x, a4.y, a4.z, a4.w};
        float bv[4] = {b4.x, b4.y, b4.z, b4.w};
        #pragma unroll
        for (int i = 0; i < 4; i++)
            #pragma unroll
            for (int j = 0; j < 4; j++)
                acc[i][j] = fmaf(av[i], bv[j], acc[i][j]);
    }
    {
        const float* b1k = b1 + k * HH;
        #pragma unroll
        for (int j = 0; j < 4; j++) {
            float bj = b1k[(tx << 2) + j];
            #pragma unroll
            for (int i = 0; i < 4; i++)
                H1T[((tx << 2) + j) * 64 + (ty << 2) + i] = sp(acc[i][j] + bj);
        }
    }
    __syncthreads();

    #pragma unroll
    for (int i = 0; i < 4; i++)
        #pragma unroll
        for (int j = 0; j < 4; j++) acc[i][j] = 0.0f;
    #pragma unroll 4
    for (int h = 0; h < HH; ++h) {
        float4 a4 = *(const float4*)&H1T[h * 64 + (ty << 2)];
        float4 b4 = *(const float4*)&W2T[h * 64 + (tx << 2)];
        float av[4] = {a4.x, a4.y, a4.z, a4.w};
        float bv[4] = {b4.x, b4.y, b4.z, b4.w};
        #pragma unroll
        for (int i = 0; i < 4; i++)
            #pragma unroll
            for (int j = 0; j < 4; j++)
                acc[i][j] = fmaf(av[i], bv[j], acc[i][j]);
    }
    __syncthreads();
    {
        const float* b2k = b2 + k * HH;
        #pragma unroll
        for (int j = 0; j < 4; j++) {
            float bj = b2k[(tx << 2) + j];
            #pragma unroll
            for (int i = 0; i < 4; i++)
                H1T[((tx << 2) + j) * 64 + (ty << 2) + i] = sp(acc[i][j] + bj);
        }
    }
    __syncthreads();

    #pragma unroll
    for (int i = 0; i < 4; i++)
        #pragma unroll
        for (int j = 0; j < 4; j++) acc[i][j] = 0.0f;
    #pragma unroll 4
    for (int g = 0; g < HH; ++g) {
        float4 a4 = *(const float4*)&H1T[g * 64 + (ty << 2)];
        float4 b4 = *(const float4*)&W3T[g * 64 + (tx << 2)];
        float av[4] = {a4.x, a4.y, a4.z, a4.w};
        float bv[4] = {b4.x, b4.y, b4.z, b4.w};
        #pragma unroll
        for (int i = 0; i < 4; i++)
            #pragma unroll
            for (int j = 0; j < 4; j++)
                acc[i][j] = fmaf(av[i], bv[j], acc[i][j]);
    }
    __syncthreads();   // done with W1T reads long ago; guard RED alias anyway
    {
        const float* b3k = b3 + k * HH;
        #pragma unroll
        for (int i = 0; i < 4; i++) {
            int row = r0 + (ty << 2) + i;
            float fv[4];
            #pragma unroll
            for (int j = 0; j < 4; j++) fv[j] = acc[i][j] + b3k[(tx << 2) + j];

            __nv_bfloat16 h[4], l[4];
            #pragma unroll
            for (int j = 0; j < 4; j++) {
                h[j] = __float2bfloat16(fv[j]);
                l[j] = __float2bfloat16(fv[j] - __bfloat162float(h[j]));
            }
            __nv_bfloat162 hp0 = __halves2bfloat162(h[0], h[1]);
            __nv_bfloat162 hp1 = __halves2bfloat162(h[2], h[3]);
            __nv_bfloat162 lp0 = __halves2bfloat162(l[0], l[1]);
            __nv_bfloat162 lp1 = __halves2bfloat162(l[2], l[3]);

            __nv_bfloat16* rowp = dsth + (size_t)row * KS + (tx << 2);
            *(__nv_bfloat162*)(rowp + 0) = hp0;
            *(__nv_bfloat162*)(rowp + 2) = hp1;
            if (isx) {  // A side (fx): [hi, hi, lo]
                *(__nv_bfloat162*)(rowp + 64)  = hp0;
                *(__nv_bfloat162*)(rowp + 66)  = hp1;
                *(__nv_bfloat162*)(rowp + 128) = lp0;
                *(__nv_bfloat162*)(rowp + 130) = lp1;
            } else {    // B side (fz): [hi, lo, hi]
                *(__nv_bfloat162*)(rowp + 64)  = lp0;
                *(__nv_bfloat162*)(rowp + 66)  = lp1;
                *(__nv_bfloat162*)(rowp + 128) = hp0;
                *(__nv_bfloat162*)(rowp + 130) = hp1;
            }
            RED[((ty << 2) + i) * 16 + tx] =
                fv[0] * fv[0] + fv[1] * fv[1] + fv[2] * fv[2] + fv[3] * fv[3];
        }
    }
    __syncthreads();
    if (t < 64) {
        float s = 0.0f;
        #pragma unroll
        for (int q = 0; q < 16; q++) s += RED[t * 16 + q];
        sdst[r0 + t] = s;
    }
}

// =====================================================================
// Kernel B: mma.sync bf16 pairwise GEMM + fused RBF epilogue.
// CTA: 256 threads (8 warps), tile 128n x 64m, warp tile 32n x 32m.
// K pipelined in 64-element chunks (9 total), 4-stage ring,
// ONE barrier per chunk (CUTLASS-style), 2 CTAs/SM.
// =====================================================================
#define NT 128
#define MT 64
#define NSTG 4
#define A_STB (128 * 128)        // 16384
#define B_STB (64 * 128)         // 8192
#define STG_B (A_STB + B_STB)    // 24576
#define OFF_SN2 0                // 3*128 f32
#define OFF_SM2 1536             // 3*64 f32
#define OFF_ST2 2304
#define SMEM_TOT2 (OFF_ST2 + NSTG * STG_B)   // 100608

__device__ __forceinline__ void load_chunk(int c, int n0, int m0,
                                           uint32_t stage, int t) {
    int k = c / 3, kc = c % 3;
    const __nv_bfloat16* gA = g_fxh + ((size_t)k * NN + n0) * KS + kc * 64;
    const __nv_bfloat16* gB = g_fzh + ((size_t)k * MM + m0) * KS + kc * 64;
    #pragma unroll
    for (int i = 0; i < 4; i++) {
        int q = t + i * 256;
        int r = q >> 3, cc = q & 7;
        cp16(stage + r * 128 + (uint32_t)((cc ^ (r & 7)) << 4),
             (const char*)(gA + (size_t)r * KS) + cc * 16);
    }
    #pragma unroll
    for (int i = 0; i < 2; i++) {
        int q = t + i * 256;
        int r = q >> 3, cc = q & 7;
        cp16(stage + A_STB + r * 128 + (uint32_t)((cc ^ (r & 7)) << 4),
             (const char*)(gB + (size_t)r * KS) + cc * 16);
    }
}

__global__ __launch_bounds__(256, 2) void pair_kernel(
    const float* __restrict__ log_sigma, const float* __restrict__ kw,
    float* __restrict__ out) {
    extern __shared__ char sm8[];
    const uint32_t sb = smem_u32_of(sm8);
    float* snS = (float*)(sm8 + OFF_SN2);
    float* smS = (float*)(sm8 + OFF_SM2);

    const int t = threadIdx.x;
    const int w = t >> 5, lane = t & 31;
    const int quad = lane >> 2, qid = lane & 3;
    const int wn = w & 3, wm = w >> 2;       // 4 over n, 2 over m
    const int nb = wn * 32, mb = wm * 32;
    const int m0 = blockIdx.x * MT;
    const int n0 = blockIdx.y * NT;

    for (int q = t; q < 3 * 128; q += 256)
        snS[q] = g_sn[(q >> 7) * NN + n0 + (q & 127)];
    for (int q = t; q < 3 * 64; q += 256)
        smS[q] = g_sm[(q >> 6) * MM + m0 + (q & 63)];

    float w0r = kw[0], w1r = kw[1], w2r = kw[2];
    float wmax = fmaxf(fmaxf(w0r, w1r), w2r);
    float ew0 = __expf(w0r - wmax), ew1 = __expf(w1r - wmax), ew2 = __expf(w2r - wmax);
    float winv = 1.0f / (ew0 + ew1 + ew2);
    float wkv[3] = {ew0 * winv, ew1 * winv, ew2 * winv};
    float c1[3];
    #pragma unroll
    for (int k = 0; k < 3; k++)
        c1[k] = 0.5f * exp2f(-log_sigma[k] * 3.3219280948873623f);

    // prologue: fill NSTG-1 = 3 stages (chunks 0..2)
    #pragma unroll
    for (int c = 0; c < NSTG - 1; c++) {
        load_chunk(c, n0, m0, sb + OFF_ST2 + c * STG_B, t);
        cp_commit();
    }

    float res[2][4][4];
    #pragma unroll
    for (int mi = 0; mi < 2; mi++)
        #pragma unroll
        for (int nj = 0; nj < 4; nj++)
            #pragma unroll
            for (int r = 0; r < 4; r++) res[mi][nj][r] = 0.0f;

    float acc[2][4][4];

    const int a_row = nb + (lane & 15);
    const int a_cb  = lane >> 4;
    const int b_row = mb + ((lane >> 4) << 3) + (lane & 7);
    const int b_cb  = (lane >> 3) & 1;

    for (int c = 0; c < 9; c++) {
        // chunk c complete when all but the newest NSTG-2 groups have drained
        cp_wait<NSTG - 2>();
        __syncthreads();

        // issue loads for chunk c+NSTG-1 into the stage freed last iteration
        if (c + NSTG - 1 < 9) {
            load_chunk(c + NSTG - 1, n0, m0,
                       sb + OFF_ST2 + (uint32_t)((c + NSTG - 1) & (NSTG - 1)) * STG_B, t);
        }
        cp_commit();   // commit (possibly empty) keeps group accounting exact

        if (c % 3 == 0) {
            #pragma unroll
            for (int mi = 0; mi < 2; mi++)
                #pragma unroll
                for (int nj = 0; nj < 4; nj++)
                    #pragma unroll
                    for (int r = 0; r < 4; r++) acc[mi][nj][r] = 0.0f;
        }

        const uint32_t a_base = sb + OFF_ST2 + (uint32_t)(c & (NSTG - 1)) * STG_B;
        const uint32_t b_base = a_base + A_STB;

        #pragma unroll
        for (int ks = 0; ks < 4; ks++) {
            uint32_t af[2][4];
            #pragma unroll
            for (int mi = 0; mi < 2; mi++) {
                int row = a_row + mi * 16;
                int cc = (2 * ks + a_cb) ^ (row & 7);
                ldsm4(af[mi], a_base + row * 128 + (cc << 4));
            }
            uint32_t bf[2][4];
            #pragma unroll
            for (int nj2 = 0; nj2 < 2; nj2++) {
                int row = b_row + nj2 * 16;
                int cc = (2 * ks + b_cb) ^ (row & 7);
                ldsm4(bf[nj2], b_base + row * 128 + (cc << 4));
            }
            #pragma unroll
            for (int mi = 0; mi < 2; mi++)
                #pragma unroll
                for (int nj2 = 0; nj2 < 2; nj2++) {
                    mma_bf16(acc[mi][2 * nj2 + 0], af[mi], bf[nj2][0], bf[nj2][1]);
                    mma_bf16(acc[mi][2 * nj2 + 1], af[mi], bf[nj2][2], bf[nj2][3]);
                }
        }

        if (c % 3 == 2) {
            int k = c / 3;
            float c1k = c1[k], c2k = 2.0f * c1k, wkk = wkv[k];
            float pn[2][2];
            #pragma unroll
            for (int mi = 0; mi < 2; mi++) {
                pn[mi][0] = c1k * snS[k * 128 + nb + mi * 16 + quad];
                pn[mi][1] = c1k * snS[k * 128 + nb + mi * 16 + quad + 8];
            }
            #pragma unroll
            for (int nj = 0; nj < 4; nj++) {
                float2 pm2 = *(float2*)&smS[k * 64 + mb + nj * 8 + 2 * qid];
                float pm0 = c1k * pm2.x, pm1 = c1k * pm2.y;
                #pragma unroll
                for (int mi = 0; mi < 2; mi++) {
                    float g0 = fminf(fmaf(c2k, acc[mi][nj][0], -(pn[mi][0] + pm0)), 0.0f);
                    float g1 = fminf(fmaf(c2k, acc[mi][nj][1], -(pn[mi][0] + pm1)), 0.0f);
                    float g2 = fminf(fmaf(c2k, acc[mi][nj][2], -(pn[mi][1] + pm0)), 0.0f);
                    float g3 = fminf(fmaf(c2k, acc[mi][nj][3], -(pn[mi][1] + pm1)), 0.0f);
                    res[mi][nj][0] = fmaf(wkk, __expf(g0), res[mi][nj][0]);
                    res[mi][nj][1] = fmaf(wkk, __expf(g1), res[mi][nj][1]);
                    res[mi][nj][2] = fmaf(wkk, __expf(g2), res[mi][nj][2]);
                    res[mi][nj][3] = fmaf(wkk, __expf(g3), res[mi][nj][3]);
                }
            }
        }
    }

    // store: rows = n, cols = m (contiguous float2 along m)
    #pragma unroll
    for (int mi = 0; mi < 2; mi++) {
        int nrow = n0 + nb + mi * 16 + quad;
        #pragma unroll
        for (int nj = 0; nj < 4; nj++) {
            float* p0 = out + (size_t)nrow * MM + m0 + mb + nj * 8 + 2 * qid;
            *(float2*)p0 = make_float2(res[mi][nj][0], res[mi][nj][1]);
            float* p1 = p0 + (size_t)8 * MM;
            *(float2*)p1 = make_float2(res[mi][nj][2], res[mi][nj][3]);
        }
    }
}

extern "C" void kernel_launch(void* const* d_in, const int* in_sizes, int n_in,
                              void* d_out, int out_size) {
    const float* x  = (const float*)d_in[0];
    const float* z  = (const float*)d_in[1];
    const float* W1 = (const float*)d_in[2];
    const float* b1 = (const float*)d_in[3];
    const float* W2 = (const float*)d_in[4];
    const float* b2 = (const float*)d_in[5];
    const float* W3 = (const float*)d_in[6];
    const float* b3 = (const float*)d_in[7];
    const float* ls = (const float*)d_in[8];
    const float* kwp = (const float*)d_in[9];
    float* out = (float*)d_out;

    cudaFuncSetAttribute(phi_kernel, cudaFuncAttributeMaxDynamicSharedMemorySize, 28672 * 4);
    cudaFuncSetAttribute(pair_kernel, cudaFuncAttributeMaxDynamicSharedMemorySize, SMEM_TOT2);

    phi_kernel<<<dim3(320, 3), 256, 28672 * 4>>>(x, z, W1, b1, W2, b2, W3, b3);
    pair_kernel<<<dim3(MM / MT, NN / NT), 256, SMEM_TOT2>>>(ls, kwp, out);
}

// round 7
// speedup vs baseline: 1.6062x; 1.0016x over previous
#include <cuda_runtime.h>
#include <cuda_bf16.h>
#include <math.h>
#include <stdint.h>

#define KK 3
#define NN 16384
#define MM 4096
#define DD 128
#define HH 64
#define KS 192   // split reduction dim: 3 x 64 bf16

// Scratch (device globals: allocation-free rule)
// fx = mma-A side (n rows): [hi, hi, lo]; fz = mma-B side (m rows): [hi, lo, hi]
// dot = hi*hi + hi*lo + lo*hi
__device__ __nv_bfloat16 g_fxh[KK * NN * KS];
__device__ __nv_bfloat16 g_fzh[KK * MM * KS];
__device__ float g_sn[KK * NN];
__device__ float g_sm[KK * MM];

__device__ __forceinline__ float sp(float v) {
    return fmaxf(v, 0.0f) + log1pf(__expf(-fabsf(v)));
}

// ======================= async / mma helpers (sm_80 PTX only) =======================
__device__ __forceinline__ uint32_t smem_u32_of(const void* p) {
    return (uint32_t)__cvta_generic_to_shared(p);
}
__device__ __forceinline__ void cp16(uint32_t dst, const void* src) {
    asm volatile("cp.async.cg.shared.global [%0], [%1], 16;" :: "r"(dst), "l"(src));
}
__device__ __forceinline__ void cp_commit() {
    asm volatile("cp.async.commit_group;" ::: "memory");
}
template <int N_>
__device__ __forceinline__ void cp_wait() {
    asm volatile("cp.async.wait_group %0;" :: "n"(N_) : "memory");
}
__device__ __forceinline__ void ldsm4(uint32_t* f, uint32_t addr) {
    asm volatile("ldmatrix.sync.aligned.m8n8.x4.shared.b16 {%0,%1,%2,%3}, [%4];"
                 : "=r"(f[0]), "=r"(f[1]), "=r"(f[2]), "=r"(f[3]) : "r"(addr));
}
__device__ __forceinline__ void mma_bf16(float* c, const uint32_t* a, uint32_t b0, uint32_t b1) {
    asm volatile(
        "mma.sync.aligned.m16n8k16.row.col.f32.bf16.bf16.f32 "
        "{%0,%1,%2,%3}, {%4,%5,%6,%7}, {%8,%9}, {%0,%1,%2,%3};"
        : "+f"(c[0]), "+f"(c[1]), "+f"(c[2]), "+f"(c[3])
        : "r"(a[0]), "r"(a[1]), "r"(a[2]), "r"(a[3]), "r"(b0), "r"(b1));
}

// =====================================================================
// Kernel A: phi MLP -> bf16 hi/lo split features + fp32 norms.
// RED aliases W1T -> smem 114688 B -> 2 CTAs/SM.
// =====================================================================
__global__ __launch_bounds__(256, 2) void phi_kernel(
    const float* __restrict__ x, const float* __restrict__ z,
    const float* __restrict__ W1, const float* __restrict__ b1,
    const float* __restrict__ W2, const float* __restrict__ b2,
    const float* __restrict__ W3, const float* __restrict__ b3) {
    extern __shared__ float smem[];
    float* XT  = smem;           // [128][64]
    float* W1T = smem + 8192;    // [128][64]
    float* W2T = smem + 16384;   // [64][64]
    float* W3T = smem + 20480;   // [64][64]
    float* H1T = smem + 24576;   // [64][64]
    float* RED = W1T;            // alias: [64][16], used after GEMM3 only

    const int t  = threadIdx.x;
    const int tx = t & 15, ty = t >> 4;
    const int k  = blockIdx.y;
    const int bx = blockIdx.x;
    const bool isx = (bx < NN / 64);
    const int r0 = (isx ? bx : bx - NN / 64) * 64;
    const float* src = isx ? x : z;
    __nv_bfloat16* dsth = isx ? (g_fxh + (size_t)k * NN * KS)
                              : (g_fzh + (size_t)k * MM * KS);
    float* sdst = isx ? (g_sn + k * NN) : (g_sm + k * MM);

    const float* W1k = W1 + k * HH * DD;
    for (int q = t; q < HH * DD / 4; q += 256) {
        int h = q >> 5, d4 = (q & 31) << 2;
        float4 v = *(const float4*)(W1k + h * DD + d4);
        W1T[(d4 + 0) * 64 + h] = v.x; W1T[(d4 + 1) * 64 + h] = v.y;
        W1T[(d4 + 2) * 64 + h] = v.z; W1T[(d4 + 3) * 64 + h] = v.w;
    }
    const float* W2k = W2 + k * HH * HH;
    const float* W3k = W3 + k * HH * HH;
    for (int q = t; q < HH * HH / 4; q += 256) {
        int g = q >> 4, h4 = (q & 15) << 2;
        float4 v2 = *(const float4*)(W2k + g * HH + h4);
        W2T[(h4 + 0) * 64 + g] = v2.x; W2T[(h4 + 1) * 64 + g] = v2.y;
        W2T[(h4 + 2) * 64 + g] = v2.z; W2T[(h4 + 3) * 64 + g] = v2.w;
        float4 v3 = *(const float4*)(W3k + g * HH + h4);
        W3T[(h4 + 0) * 64 + g] = v3.x; W3T[(h4 + 1) * 64 + g] = v3.y;
        W3T[(h4 + 2) * 64 + g] = v3.z; W3T[(h4 + 3) * 64 + g] = v3.w;
    }
    for (int q = t; q < 64 * DD / 4; q += 256) {
        int r = q >> 5, d4 = (q & 31) << 2;
        float4 v = *(const float4*)(src + (size_t)(r0 + r) * DD + d4);
        XT[(d4 + 0) * 64 + r] = v.x; XT[(d4 + 1) * 64 + r] = v.y;
        XT[(d4 + 2) * 64 + r] = v.z; XT[(d4 + 3) * 64 + r] = v.w;
    }
    __syncthreads();

    float acc[4][4];
    #pragma unroll
    for (int i = 0; i < 4; i++)
        #pragma unroll
        for (int j = 0; j < 4; j++) acc[i][j] = 0.0f;

    #pragma unroll 4
    for (int d = 0; d < DD; ++d) {
        float4 a4 = *(const float4*)&XT[d * 64 + (ty << 2)];
        float4 b4 = *(const float4*)&W1T[d * 64 + (tx << 2)];
        float av[4] = {a4.x, a4.y, a4.z, a4.w};
        float bv[4] = {b4.x, b4.y, b4.z, b4.w};
        #pragma unroll
        for (int i = 0; i < 4; i++)
            #pragma unroll
            for (int j = 0; j < 4; j++)
                acc[i][j] = fmaf(av[i], bv[j], acc[i][j]);
    }
    {
        const float* b1k = b1 + k * HH;
        #pragma unroll
        for (int j = 0; j < 4; j++) {
            float bj = b1k[(tx << 2) + j];
            #pragma unroll
            for (int i = 0; i < 4; i++)
                H1T[((tx << 2) + j) * 64 + (ty << 2) + i] = sp(acc[i][j] + bj);
        }
    }
    __syncthreads();

    #pragma unroll
    for (int i = 0; i < 4; i++)
        #pragma unroll
        for (int j = 0; j < 4; j++) acc[i][j] = 0.0f;
    #pragma unroll 4
    for (int h = 0; h < HH; ++h) {
        float4 a4 = *(const float4*)&H1T[h * 64 + (ty << 2)];
        float4 b4 = *(const float4*)&W2T[h * 64 + (tx << 2)];
        float av[4] = {a4.x, a4.y, a4.z, a4.w};
        float bv[4] = {b4.x, b4.y, b4.z, b4.w};
        #pragma unroll
        for (int i = 0; i < 4; i++)
            #pragma unroll
            for (int j = 0; j < 4; j++)
                acc[i][j] = fmaf(av[i], bv[j], acc[i][j]);
    }
    __syncthreads();
    {
        const float* b2k = b2 + k * HH;
        #pragma unroll
        for (int j = 0; j < 4; j++) {
            float bj = b2k[(tx << 2) + j];
            #pragma unroll
            for (int i = 0; i < 4; i++)
                H1T[((tx << 2) + j) * 64 + (ty << 2) + i] = sp(acc[i][j] + bj);
        }
    }
    __syncthreads();

    #pragma unroll
    for (int i = 0; i < 4; i++)
        #pragma unroll
        for (int j = 0; j < 4; j++) acc[i][j] = 0.0f;
    #pragma unroll 4
    for (int g = 0; g < HH; ++g) {
        float4 a4 = *(const float4*)&H1T[g * 64 + (ty << 2)];
        float4 b4 = *(const float4*)&W3T[g * 64 + (tx << 2)];
        float av[4] = {a4.x, a4.y, a4.z, a4.w};
        float bv[4] = {b4.x, b4.y, b4.z, b4.w};
        #pragma unroll
        for (int i = 0; i < 4; i++)
            #pragma unroll
            for (int j = 0; j < 4; j++)
                acc[i][j] = fmaf(av[i], bv[j], acc[i][j]);
    }
    __syncthreads();   // guard RED alias
    {
        const float* b3k = b3 + k * HH;
        #pragma unroll
        for (int i = 0; i < 4; i++) {
            int row = r0 + (ty << 2) + i;
            float fv[4];
            #pragma unroll
            for (int j = 0; j < 4; j++) fv[j] = acc[i][j] + b3k[(tx << 2) + j];

            __nv_bfloat16 h[4], l[4];
            #pragma unroll
            for (int j = 0; j < 4; j++) {
                h[j] = __float2bfloat16(fv[j]);
                l[j] = __float2bfloat16(fv[j] - __bfloat162float(h[j]));
            }
            __nv_bfloat162 hp0 = __halves2bfloat162(h[0], h[1]);
            __nv_bfloat162 hp1 = __halves2bfloat162(h[2], h[3]);
            __nv_bfloat162 lp0 = __halves2bfloat162(l[0], l[1]);
            __nv_bfloat162 lp1 = __halves2bfloat162(l[2], l[3]);

            __nv_bfloat16* rowp = dsth + (size_t)row * KS + (tx << 2);
            *(__nv_bfloat162*)(rowp + 0) = hp0;
            *(__nv_bfloat162*)(rowp + 2) = hp1;
            if (isx) {  // A side (fx): [hi, hi, lo]
                *(__nv_bfloat162*)(rowp + 64)  = hp0;
                *(__nv_bfloat162*)(rowp + 66)  = hp1;
                *(__nv_bfloat162*)(rowp + 128) = lp0;
                *(__nv_bfloat162*)(rowp + 130) = lp1;
            } else {    // B side (fz): [hi, lo, hi]
                *(__nv_bfloat162*)(rowp + 64)  = lp0;
                *(__nv_bfloat162*)(rowp + 66)  = lp1;
                *(__nv_bfloat162*)(rowp + 128) = hp0;
                *(__nv_bfloat162*)(rowp + 130) = hp1;
            }
            RED[((ty << 2) + i) * 16 + tx] =
                fv[0] * fv[0] + fv[1] * fv[1] + fv[2] * fv[2] + fv[3] * fv[3];
        }
    }
    __syncthreads();
    if (t < 64) {
        float s = 0.0f;
        #pragma unroll
        for (int q = 0; q < 16; q++) s += RED[t * 16 + q];
        sdst[r0 + t] = s;
    }
}

// =====================================================================
// Kernel B: mma.sync bf16 pairwise GEMM + fused RBF epilogue.
// CTA: 256 threads (8 warps), tile 128n x 64m, warp tile 32n x 32m.
// K pipelined in 64-element chunks (9 total), 4-stage ring, single
// barrier per chunk, explicit ks-level frag double-buffering, 2 CTAs/SM.
// =====================================================================
#define NT 128
#define MT 64
#define NSTG 4
#define A_STB (128 * 128)        // 16384
#define B_STB (64 * 128)         // 8192
#define STG_B (A_STB + B_STB)    // 24576
#define OFF_SN2 0                // 3*128 f32
#define OFF_SM2 1536             // 3*64 f32
#define OFF_ST2 2304
#define SMEM_TOT2 (OFF_ST2 + NSTG * STG_B)   // 100608

__device__ __forceinline__ void load_chunk(int c, int n0, int m0,
                                           uint32_t stage, int t) {
    int k = c / 3, kc = c % 3;
    const __nv_bfloat16* gA = g_fxh + ((size_t)k * NN + n0) * KS + kc * 64;
    const __nv_bfloat16* gB = g_fzh + ((size_t)k * MM + m0) * KS + kc * 64;
    #pragma unroll
    for (int i = 0; i < 4; i++) {
        int q = t + i * 256;
        int r = q >> 3, cc = q & 7;
        cp16(stage + r * 128 + (uint32_t)((cc ^ (r & 7)) << 4),
             (const char*)(gA + (size_t)r * KS) + cc * 16);
    }
    #pragma unroll
    for (int i = 0; i < 2; i++) {
        int q = t + i * 256;
        int r = q >> 3, cc = q & 7;
        cp16(stage + A_STB + r * 128 + (uint32_t)((cc ^ (r & 7)) << 4),
             (const char*)(gB + (size_t)r * KS) + cc * 16);
    }
}

__global__ __launch_bounds__(256, 2) void pair_kernel(
    const float* __restrict__ log_sigma, const float* __restrict__ kw,
    float* __restrict__ out) {
    extern __shared__ char sm8[];
    const uint32_t sb = smem_u32_of(sm8);
    float* snS = (float*)(sm8 + OFF_SN2);
    float* smS = (float*)(sm8 + OFF_SM2);

    const int t = threadIdx.x;
    const int w = t >> 5, lane = t & 31;
    const int quad = lane >> 2, qid = lane & 3;
    const int wn = w & 3, wm = w >> 2;       // 4 over n, 2 over m
    const int nb = wn * 32, mb = wm * 32;
    const int m0 = blockIdx.x * MT;
    const int n0 = blockIdx.y * NT;

    for (int q = t; q < 3 * 128; q += 256)
        snS[q] = g_sn[(q >> 7) * NN + n0 + (q & 127)];
    for (int q = t; q < 3 * 64; q += 256)
        smS[q] = g_sm[(q >> 6) * MM + m0 + (q & 63)];

    float w0r = kw[0], w1r = kw[1], w2r = kw[2];
    float wmax = fmaxf(fmaxf(w0r, w1r), w2r);
    float ew0 = __expf(w0r - wmax), ew1 = __expf(w1r - wmax), ew2 = __expf(w2r - wmax);
    float winv = 1.0f / (ew0 + ew1 + ew2);
    float wkv[3] = {ew0 * winv, ew1 * winv, ew2 * winv};
    float c1[3];
    #pragma unroll
    for (int k = 0; k < 3; k++)
        c1[k] = 0.5f * exp2f(-log_sigma[k] * 3.3219280948873623f);

    // prologue: fill NSTG-1 = 3 stages (chunks 0..2)
    #pragma unroll
    for (int c = 0; c < NSTG - 1; c++) {
        load_chunk(c, n0, m0, sb + OFF_ST2 + c * STG_B, t);
        cp_commit();
    }

    float res[2][4][4];
    #pragma unroll
    for (int mi = 0; mi < 2; mi++)
        #pragma unroll
        for (int nj = 0; nj < 4; nj++)
            #pragma unroll
            for (int r = 0; r < 4; r++) res[mi][nj][r] = 0.0f;

    float acc[2][4][4];

    // precomputed per-thread swizzled ldsm offsets (invariant across chunks)
    // A: rows a_row, a_row+16 share (row&7); same for B
    const int a_row = nb + (lane & 15);
    const int a_cb  = lane >> 4;
    const int b_row = mb + ((lane >> 4) << 3) + (lane & 7);
    const int b_cb  = (lane >> 3) & 1;
    const uint32_t a_r7x = (uint32_t)((a_row & 7) << 4);
    const uint32_t b_r7x = (uint32_t)((b_row & 7) << 4);
    uint32_t aoff[4], boff[4];
    #pragma unroll
    for (int ks = 0; ks < 4; ks++) {
        aoff[ks] = (uint32_t)(a_row * 128) + ((uint32_t)((2 * ks + a_cb) << 4) ^ a_r7x);
        boff[ks] = (uint32_t)(b_row * 128) + ((uint32_t)((2 * ks + b_cb) << 4) ^ b_r7x);
    }

    for (int c = 0; c < 9; c++) {
        cp_wait<NSTG - 2>();
        __syncthreads();

        const uint32_t a_base = sb + OFF_ST2 + (uint32_t)(c & (NSTG - 1)) * STG_B;
        const uint32_t b_base = a_base + A_STB;

        // prefetch frag group ks=0 (double-buffered)
        uint32_t af[2][2][4], bf[2][2][4];
        ldsm4(af[0][0], a_base + aoff[0]);
        ldsm4(af[0][1], a_base + aoff[0] + 16 * 128);
        ldsm4(bf[0][0], b_base + boff[0]);
        ldsm4(bf[0][1], b_base + boff[0] + 16 * 128);

        // issue next chunk's loads into the stage freed last iteration
        if (c + NSTG - 1 < 9) {
            load_chunk(c + NSTG - 1, n0, m0,
                       sb + OFF_ST2 + (uint32_t)((c + NSTG - 1) & (NSTG - 1)) * STG_B, t);
        }
        cp_commit();

        if (c % 3 == 0) {
            #pragma unroll
            for (int mi = 0; mi < 2; mi++)
                #pragma unroll
                for (int nj = 0; nj < 4; nj++)
                    #pragma unroll
                    for (int r = 0; r < 4; r++) acc[mi][nj][r] = 0.0f;
        }

        #pragma unroll
        for (int ks = 0; ks < 4; ks++) {
            int cur = ks & 1, nxt = cur ^ 1;
            if (ks < 3) {
                ldsm4(af[nxt][0], a_base + aoff[ks + 1]);
                ldsm4(af[nxt][1], a_base + aoff[ks + 1] + 16 * 128);
                ldsm4(bf[nxt][0], b_base + boff[ks + 1]);
                ldsm4(bf[nxt][1], b_base + boff[ks + 1] + 16 * 128);
            }
            #pragma unroll
            for (int mi = 0; mi < 2; mi++)
                #pragma unroll
                for (int nj2 = 0; nj2 < 2; nj2++) {
                    mma_bf16(acc[mi][2 * nj2 + 0], af[cur][mi], bf[cur][nj2][0], bf[cur][nj2][1]);
                    mma_bf16(acc[mi][2 * nj2 + 1], af[cur][mi], bf[cur][nj2][2], bf[cur][nj2][3]);
                }
        }

        if (c % 3 == 2) {
            int k = c / 3;
            float c1k = c1[k], c2k = 2.0f * c1k, wkk = wkv[k];
            float pn[2][2];
            #pragma unroll
            for (int mi = 0; mi < 2; mi++) {
                pn[mi][0] = c1k * snS[k * 128 + nb + mi * 16 + quad];
                pn[mi][1] = c1k * snS[k * 128 + nb + mi * 16 + quad + 8];
            }
            #pragma unroll
            for (int nj = 0; nj < 4; nj++) {
                float2 pm2 = *(float2*)&smS[k * 64 + mb + nj * 8 + 2 * qid];
                float pm0 = c1k * pm2.x, pm1 = c1k * pm2.y;
                #pragma unroll
                for (int mi = 0; mi < 2; mi++) {
                    float g0 = fminf(fmaf(c2k, acc[mi][nj][0], -(pn[mi][0] + pm0)), 0.0f);
                    float g1 = fminf(fmaf(c2k, acc[mi][nj][1], -(pn[mi][0] + pm1)), 0.0f);
                    float g2 = fminf(fmaf(c2k, acc[mi][nj][2], -(pn[mi][1] + pm0)), 0.0f);
                    float g3 = fminf(fmaf(c2k, acc[mi][nj][3], -(pn[mi][1] + pm1)), 0.0f);
                    res[mi][nj][0] = fmaf(wkk, __expf(g0), res[mi][nj][0]);
                    res[mi][nj][1] = fmaf(wkk, __expf(g1), res[mi][nj][1]);
                    res[mi][nj][2] = fmaf(wkk, __expf(g2), res[mi][nj][2]);
                    res[mi][nj][3] = fmaf(wkk, __expf(g3), res[mi][nj][3]);
                }
            }
        }
    }

    // store: rows = n, cols = m (contiguous float2 along m)
    #pragma unroll
    for (int mi = 0; mi < 2; mi++) {
        int nrow = n0 + nb + mi * 16 + quad;
        #pragma unroll
        for (int nj = 0; nj < 4; nj++) {
            float* p0 = out + (size_t)nrow * MM + m0 + mb + nj * 8 + 2 * qid;
            *(float2*)p0 = make_float2(res[mi][nj][0], res[mi][nj][1]);
            float* p1 = p0 + (size_t)8 * MM;
            *(float2*)p1 = make_float2(res[mi][nj][2], res[mi][nj][3]);
        }
    }
}

extern "C" void kernel_launch(void* const* d_in, const int* in_sizes, int n_in,
                              void* d_out, int out_size) {
    const float* x  = (const float*)d_in[0];
    const float* z  = (const float*)d_in[1];
    const float* W1 = (const float*)d_in[2];
    const float* b1 = (const float*)d_in[3];
    const float* W2 = (const float*)d_in[4];
    const float* b2 = (const float*)d_in[5];
    const float* W3 = (const float*)d_in[6];
    const float* b3 = (const float*)d_in[7];
    const float* ls = (const float*)d_in[8];
    const float* kwp = (const float*)d_in[9];
    float* out = (float*)d_out;

    cudaFuncSetAttribute(phi_kernel, cudaFuncAttributeMaxDynamicSharedMemorySize, 28672 * 4);
    cudaFuncSetAttribute(pair_kernel, cudaFuncAttributeMaxDynamicSharedMemorySize, SMEM_TOT2);

    phi_kernel<<<dim3(320, 3), 256, 28672 * 4>>>(x, z, W1, b1, W2, b2, W3, b3);
    pair_kernel<<<dim3(MM / MT, NN / NT), 256, SMEM_TOT2>>>(ls, kwp, out);
}

// round 8
// speedup vs baseline: 2.4464x; 1.5232x over previous
#include <cuda_runtime.h>
#include <cuda_fp16.h>
#include <math.h>
#include <stdint.h>

#define KK 3
#define NN 16384
#define MM 4096
#define DD 128
#define HH 64

// Scratch (device globals: allocation-free rule)
// Features stored as fp16; norms computed IN FP32 FROM THE FP16-ROUNDED
// values so that sq = sn + sm - 2*dot == |x_hat - z_hat|^2 (consistency:
// rounding error only enters scaled by pair distance, where exp decays).
__device__ __half g_fxh[KK * NN * HH];
__device__ __half g_fzh[KK * MM * HH];
__device__ float g_sn[KK * NN];
__device__ float g_sm[KK * MM];

__device__ __forceinline__ float sp(float v) {
    return fmaxf(v, 0.0f) + log1pf(__expf(-fabsf(v)));
}

// ======================= async / mma helpers (sm_80 PTX only) =======================
__device__ __forceinline__ uint32_t smem_u32_of(const void* p) {
    return (uint32_t)__cvta_generic_to_shared(p);
}
__device__ __forceinline__ void cp16(uint32_t dst, const void* src) {
    asm volatile("cp.async.cg.shared.global [%0], [%1], 16;" :: "r"(dst), "l"(src));
}
__device__ __forceinline__ void cp_commit() {
    asm volatile("cp.async.commit_group;" ::: "memory");
}
template <int N_>
__device__ __forceinline__ void cp_wait() {
    asm volatile("cp.async.wait_group %0;" :: "n"(N_) : "memory");
}
__device__ __forceinline__ void ldsm4(uint32_t* f, uint32_t addr) {
    asm volatile("ldmatrix.sync.aligned.m8n8.x4.shared.b16 {%0,%1,%2,%3}, [%4];"
                 : "=r"(f[0]), "=r"(f[1]), "=r"(f[2]), "=r"(f[3]) : "r"(addr));
}
__device__ __forceinline__ void mma_f16(float* c, const uint32_t* a, uint32_t b0, uint32_t b1) {
    asm volatile(
        "mma.sync.aligned.m16n8k16.row.col.f32.f16.f16.f32 "
        "{%0,%1,%2,%3}, {%4,%5,%6,%7}, {%8,%9}, {%0,%1,%2,%3};"
        : "+f"(c[0]), "+f"(c[1]), "+f"(c[2]), "+f"(c[3])
        : "r"(a[0]), "r"(a[1]), "r"(a[2]), "r"(a[3]), "r"(b0), "r"(b1));
}

// =====================================================================
// Kernel A: phi MLP -> fp16 features + fp32 norms of the ROUNDED values.
// RED aliases W1T -> smem 114688 B -> 2 CTAs/SM.
// =====================================================================
__global__ __launch_bounds__(256, 2) void phi_kernel(
    const float* __restrict__ x, const float* __restrict__ z,
    const float* __restrict__ W1, const float* __restrict__ b1,
    const float* __restrict__ W2, const float* __restrict__ b2,
    const float* __restrict__ W3, const float* __restrict__ b3) {
    extern __shared__ float smem[];
    float* XT  = smem;           // [128][64]
    float* W1T = smem + 8192;    // [128][64]
    float* W2T = smem + 16384;   // [64][64]
    float* W3T = smem + 20480;   // [64][64]
    float* H1T = smem + 24576;   // [64][64]
    float* RED = W1T;            // alias: [64][16], used after GEMM3 only

    const int t  = threadIdx.x;
    const int tx = t & 15, ty = t >> 4;
    const int k  = blockIdx.y;
    const int bx = blockIdx.x;
    const bool isx = (bx < NN / 64);
    const int r0 = (isx ? bx : bx - NN / 64) * 64;
    const float* src = isx ? x : z;
    __half* dsth = isx ? (g_fxh + (size_t)k * NN * HH)
                       : (g_fzh + (size_t)k * MM * HH);
    float* sdst = isx ? (g_sn + k * NN) : (g_sm + k * MM);

    const float* W1k = W1 + k * HH * DD;
    for (int q = t; q < HH * DD / 4; q += 256) {
        int h = q >> 5, d4 = (q & 31) << 2;
        float4 v = *(const float4*)(W1k + h * DD + d4);
        W1T[(d4 + 0) * 64 + h] = v.x; W1T[(d4 + 1) * 64 + h] = v.y;
        W1T[(d4 + 2) * 64 + h] = v.z; W1T[(d4 + 3) * 64 + h] = v.w;
    }
    const float* W2k = W2 + k * HH * HH;
    const float* W3k = W3 + k * HH * HH;
    for (int q = t; q < HH * HH / 4; q += 256) {
        int g = q >> 4, h4 = (q & 15) << 2;
        float4 v2 = *(const float4*)(W2k + g * HH + h4);
        W2T[(h4 + 0) * 64 + g] = v2.x; W2T[(h4 + 1) * 64 + g] = v2.y;
        W2T[(h4 + 2) * 64 + g] = v2.z; W2T[(h4 + 3) * 64 + g] = v2.w;
        float4 v3 = *(const float4*)(W3k + g * HH + h4);
        W3T[(h4 + 0) * 64 + g] = v3.x; W3T[(h4 + 1) * 64 + g] = v3.y;
        W3T[(h4 + 2) * 64 + g] = v3.z; W3T[(h4 + 3) * 64 + g] = v3.w;
    }
    for (int q = t; q < 64 * DD / 4; q += 256) {
        int r = q >> 5, d4 = (q & 31) << 2;
        float4 v = *(const float4*)(src + (size_t)(r0 + r) * DD + d4);
        XT[(d4 + 0) * 64 + r] = v.x; XT[(d4 + 1) * 64 + r] = v.y;
        XT[(d4 + 2) * 64 + r] = v.z; XT[(d4 + 3) * 64 + r] = v.w;
    }
    __syncthreads();

    float acc[4][4];
    #pragma unroll
    for (int i = 0; i < 4; i++)
        #pragma unroll
        for (int j = 0; j < 4; j++) acc[i][j] = 0.0f;

    #pragma unroll 4
    for (int d = 0; d < DD; ++d) {
        float4 a4 = *(const float4*)&XT[d * 64 + (ty << 2)];
        float4 b4 = *(const float4*)&W1T[d * 64 + (tx << 2)];
        float av[4] = {a4.x, a4.y, a4.z, a4.w};
        float bv[4] = {b4.x, b4.y, b4.z, b4.w};
        #pragma unroll
        for (int i = 0; i < 4; i++)
            #pragma unroll
            for (int j = 0; j < 4; j++)
                acc[i][j] = fmaf(av[i], bv[j], acc[i][j]);
    }
    {
        const float* b1k = b1 + k * HH;
        #pragma unroll
        for (int j = 0; j < 4; j++) {
            float bj = b1k[(tx << 2) + j];
            #pragma unroll
            for (int i = 0; i < 4; i++)
                H1T[((tx << 2) + j) * 64 + (ty << 2) + i] = sp(acc[i][j] + bj);
        }
    }
    __syncthreads();

    #pragma unroll
    for (int i = 0; i < 4; i++)
        #pragma unroll
        for (int j = 0; j < 4; j++) acc[i][j] = 0.0f;
    #pragma unroll 4
    for (int h = 0; h < HH; ++h) {
        float4 a4 = *(const float4*)&H1T[h * 64 + (ty << 2)];
        float4 b4 = *(const float4*)&W2T[h * 64 + (tx << 2)];
        float av[4] = {a4.x, a4.y, a4.z, a4.w};
        float bv[4] = {b4.x, b4.y, b4.z, b4.w};
        #pragma unroll
        for (int i = 0; i < 4; i++)
            #pragma unroll
            for (int j = 0; j < 4; j++)
                acc[i][j] = fmaf(av[i], bv[j], acc[i][j]);
    }
    __syncthreads();
    {
        const float* b2k = b2 + k * HH;
        #pragma unroll
        for (int j = 0; j < 4; j++) {
            float bj = b2k[(tx << 2) + j];
            #pragma unroll
            for (int i = 0; i < 4; i++)
                H1T[((tx << 2) + j) * 64 + (ty << 2) + i] = sp(acc[i][j] + bj);
        }
    }
    __syncthreads();

    #pragma unroll
    for (int i = 0; i < 4; i++)
        #pragma unroll
        for (int j = 0; j < 4; j++) acc[i][j] = 0.0f;
    #pragma unroll 4
    for (int g = 0; g < HH; ++g) {
        float4 a4 = *(const float4*)&H1T[g * 64 + (ty << 2)];
        float4 b4 = *(const float4*)&W3T[g * 64 + (tx << 2)];
        float av[4] = {a4.x, a4.y, a4.z, a4.w};
        float bv[4] = {b4.x, b4.y, b4.z, b4.w};
        #pragma unroll
        for (int i = 0; i < 4; i++)
            #pragma unroll
            for (int j = 0; j < 4; j++)
                acc[i][j] = fmaf(av[i], bv[j], acc[i][j]);
    }
    __syncthreads();   // guard RED alias
    {
        const float* b3k = b3 + k * HH;
        #pragma unroll
        for (int i = 0; i < 4; i++) {
            int row = r0 + (ty << 2) + i;
            float fv[4], hv[4];
            __half h[4];
            #pragma unroll
            for (int j = 0; j < 4; j++) {
                fv[j] = acc[i][j] + b3k[(tx << 2) + j];
                h[j] = __float2half(fv[j]);
                hv[j] = __half2float(h[j]);   // rounded value, for norm
            }
            __half* rowp = dsth + (size_t)row * HH + (tx << 2);
            *(__half2*)(rowp + 0) = __halves2half2(h[0], h[1]);
            *(__half2*)(rowp + 2) = __halves2half2(h[2], h[3]);
            RED[((ty << 2) + i) * 16 + tx] =
                hv[0] * hv[0] + hv[1] * hv[1] + hv[2] * hv[2] + hv[3] * hv[3];
        }
    }
    __syncthreads();
    if (t < 64) {
        float s = 0.0f;
        #pragma unroll
        for (int q = 0; q < 16; q++) s += RED[t * 16 + q];
        sdst[r0 + t] = s;
    }
}

// =====================================================================
// Kernel B: mma.sync fp16 pairwise GEMM + fused RBF epilogue.
// CTA: 256 threads (8 warps), tile 128n x 64m, warp tile 32n x 32m.
// K=64 per kernel-k; 3 chunks total, all prefetched up front (3 stages),
// epilogue after every chunk. 2 CTAs/SM.
// =====================================================================
#define NT 128
#define MT 64
#define A_STB (128 * 128)        // 16384: 128 n-rows x 64 fp16
#define B_STB (64 * 128)         // 8192:  64 m-rows x 64 fp16
#define STG_B (A_STB + B_STB)    // 24576
#define OFF_SN2 0                // 3*128 f32
#define OFF_SM2 1536             // 3*64 f32
#define OFF_ST2 2304
#define SMEM_TOT2 (OFF_ST2 + 3 * STG_B)   // 76032

__device__ __forceinline__ void load_chunk(int k, int n0, int m0,
                                           uint32_t stage, int t) {
    const __half* gA = g_fxh + ((size_t)k * NN + n0) * HH;
    const __half* gB = g_fzh + ((size_t)k * MM + m0) * HH;
    #pragma unroll
    for (int i = 0; i < 4; i++) {
        int q = t + i * 256;
        int r = q >> 3, cc = q & 7;
        cp16(stage + r * 128 + (uint32_t)((cc ^ (r & 7)) << 4),
             (const char*)(gA + (size_t)r * HH) + cc * 16);
    }
    #pragma unroll
    for (int i = 0; i < 2; i++) {
        int q = t + i * 256;
        int r = q >> 3, cc = q & 7;
        cp16(stage + A_STB + r * 128 + (uint32_t)((cc ^ (r & 7)) << 4),
             (const char*)(gB + (size_t)r * HH) + cc * 16);
    }
}

__global__ __launch_bounds__(256, 2) void pair_kernel(
    const float* __restrict__ log_sigma, const float* __restrict__ kw,
    float* __restrict__ out) {
    extern __shared__ char sm8[];
    const uint32_t sb = smem_u32_of(sm8);
    float* snS = (float*)(sm8 + OFF_SN2);
    float* smS = (float*)(sm8 + OFF_SM2);

    const int t = threadIdx.x;
    const int w = t >> 5, lane = t & 31;
    const int quad = lane >> 2, qid = lane & 3;
    const int wn = w & 3, wm = w >> 2;       // 4 over n, 2 over m
    const int nb = wn * 32, mb = wm * 32;
    const int m0 = blockIdx.x * MT;
    const int n0 = blockIdx.y * NT;

    // prefetch all 3 chunks immediately
    load_chunk(0, n0, m0, sb + OFF_ST2 + 0 * STG_B, t); cp_commit();
    load_chunk(1, n0, m0, sb + OFF_ST2 + 1 * STG_B, t); cp_commit();
    load_chunk(2, n0, m0, sb + OFF_ST2 + 2 * STG_B, t); cp_commit();

    for (int q = t; q < 3 * 128; q += 256)
        snS[q] = g_sn[(q >> 7) * NN + n0 + (q & 127)];
    for (int q = t; q < 3 * 64; q += 256)
        smS[q] = g_sm[(q >> 6) * MM + m0 + (q & 63)];

    float w0r = kw[0], w1r = kw[1], w2r = kw[2];
    float wmax = fmaxf(fmaxf(w0r, w1r), w2r);
    float ew0 = __expf(w0r - wmax), ew1 = __expf(w1r - wmax), ew2 = __expf(w2r - wmax);
    float winv = 1.0f / (ew0 + ew1 + ew2);
    float wkv[3] = {ew0 * winv, ew1 * winv, ew2 * winv};
    float c1[3];
    #pragma unroll
    for (int k = 0; k < 3; k++)
        c1[k] = 0.5f * exp2f(-log_sigma[k] * 3.3219280948873623f);

    float res[2][4][4];
    #pragma unroll
    for (int mi = 0; mi < 2; mi++)
        #pragma unroll
        for (int nj = 0; nj < 4; nj++)
            #pragma unroll
            for (int r = 0; r < 4; r++) res[mi][nj][r] = 0.0f;

    // precomputed per-thread swizzled ldsm offsets
    const int a_row = nb + (lane & 15);
    const int a_cb  = lane >> 4;
    const int b_row = mb + ((lane >> 4) << 3) + (lane & 7);
    const int b_cb  = (lane >> 3) & 1;
    const uint32_t a_r7x = (uint32_t)((a_row & 7) << 4);
    const uint32_t b_r7x = (uint32_t)((b_row & 7) << 4);
    uint32_t aoff[4], boff[4];
    #pragma unroll
    for (int ks = 0; ks < 4; ks++) {
        aoff[ks] = (uint32_t)(a_row * 128) + ((uint32_t)((2 * ks + a_cb) << 4) ^ a_r7x);
        boff[ks] = (uint32_t)(b_row * 128) + ((uint32_t)((2 * ks + b_cb) << 4) ^ b_r7x);
    }

    #pragma unroll
    for (int k = 0; k < KK; k++) {
        if (k == 0)      cp_wait<2>();
        else if (k == 1) cp_wait<1>();
        else             cp_wait<0>();
        __syncthreads();

        const uint32_t a_base = sb + OFF_ST2 + (uint32_t)k * STG_B;
        const uint32_t b_base = a_base + A_STB;

        float acc[2][4][4];
        #pragma unroll
        for (int mi = 0; mi < 2; mi++)
            #pragma unroll
            for (int nj = 0; nj < 4; nj++)
                #pragma unroll
                for (int r = 0; r < 4; r++) acc[mi][nj][r] = 0.0f;

        uint32_t af[2][2][4], bf[2][2][4];
        ldsm4(af[0][0], a_base + aoff[0]);
        ldsm4(af[0][1], a_base + aoff[0] + 16 * 128);
        ldsm4(bf[0][0], b_base + boff[0]);
        ldsm4(bf[0][1], b_base + boff[0] + 16 * 128);

        #pragma unroll
        for (int ks = 0; ks < 4; ks++) {
            int cur = ks & 1, nxt = cur ^ 1;
            if (ks < 3) {
                ldsm4(af[nxt][0], a_base + aoff[ks + 1]);
                ldsm4(af[nxt][1], a_base + aoff[ks + 1] + 16 * 128);
                ldsm4(bf[nxt][0], b_base + boff[ks + 1]);
                ldsm4(bf[nxt][1], b_base + boff[ks + 1] + 16 * 128);
            }
            #pragma unroll
            for (int mi = 0; mi < 2; mi++)
                #pragma unroll
                for (int nj2 = 0; nj2 < 2; nj2++) {
                    mma_f16(acc[mi][2 * nj2 + 0], af[cur][mi], bf[cur][nj2][0], bf[cur][nj2][1]);
                    mma_f16(acc[mi][2 * nj2 + 1], af[cur][mi], bf[cur][nj2][2], bf[cur][nj2][3]);
                }
        }

        // fused RBF epilogue for kernel k
        {
            float c1k = c1[k], c2k = 2.0f * c1k, wkk = wkv[k];
            float pn[2][2];
            #pragma unroll
            for (int mi = 0; mi < 2; mi++) {
                pn[mi][0] = c1k * snS[k * 128 + nb + mi * 16 + quad];
                pn[mi][1] = c1k * snS[k * 128 + nb + mi * 16 + quad + 8];
            }
            #pragma unroll
            for (int nj = 0; nj < 4; nj++) {
                float2 pm2 = *(float2*)&smS[k * 64 + mb + nj * 8 + 2 * qid];
                float pm0 = c1k * pm2.x, pm1 = c1k * pm2.y;
                #pragma unroll
                for (int mi = 0; mi < 2; mi++) {
                    float g0 = fminf(fmaf(c2k, acc[mi][nj][0], -(pn[mi][0] + pm0)), 0.0f);
                    float g1 = fminf(fmaf(c2k, acc[mi][nj][1], -(pn[mi][0] + pm1)), 0.0f);
                    float g2 = fminf(fmaf(c2k, acc[mi][nj][2], -(pn[mi][1] + pm0)), 0.0f);
                    float g3 = fminf(fmaf(c2k, acc[mi][nj][3], -(pn[mi][1] + pm1)), 0.0f);
                    res[mi][nj][0] = fmaf(wkk, __expf(g0), res[mi][nj][0]);
                    res[mi][nj][1] = fmaf(wkk, __expf(g1), res[mi][nj][1]);
                    res[mi][nj][2] = fmaf(wkk, __expf(g2), res[mi][nj][2]);
                    res[mi][nj][3] = fmaf(wkk, __expf(g3), res[mi][nj][3]);
                }
            }
        }
    }

    // store: rows = n, cols = m (contiguous float2 along m)
    #pragma unroll
    for (int mi = 0; mi < 2; mi++) {
        int nrow = n0 + nb + mi * 16 + quad;
        #pragma unroll
        for (int nj = 0; nj < 4; nj++) {
            float* p0 = out + (size_t)nrow * MM + m0 + mb + nj * 8 + 2 * qid;
            *(float2*)p0 = make_float2(res[mi][nj][0], res[mi][nj][1]);
            float* p1 = p0 + (size_t)8 * MM;
            *(float2*)p1 = make_float2(res[mi][nj][2], res[mi][nj][3]);
        }
    }
}

extern "C" void kernel_launch(void* const* d_in, const int* in_sizes, int n_in,
                              void* d_out, int out_size) {
    const float* x  = (const float*)d_in[0];
    const float* z  = (const float*)d_in[1];
    const float* W1 = (const float*)d_in[2];
    const float* b1 = (const float*)d_in[3];
    const float* W2 = (const float*)d_in[4];
    const float* b2 = (const float*)d_in[5];
    const float* W3 = (const float*)d_in[6];
    const float* b3 = (const float*)d_in[7];
    const float* ls = (const float*)d_in[8];
    const float* kwp = (const float*)d_in[9];
    float* out = (float*)d_out;

    cudaFuncSetAttribute(phi_kernel, cudaFuncAttributeMaxDynamicSharedMemorySize, 28672 * 4);
    cudaFuncSetAttribute(pair_kernel, cudaFuncAttributeMaxDynamicSharedMemorySize, SMEM_TOT2);

    phi_kernel<<<dim3(320, 3), 256, 28672 * 4>>>(x, z, W1, b1, W2, b2, W3, b3);
    pair_kernel<<<dim3(MM / MT, NN / NT), 256, SMEM_TOT2>>>(ls, kwp, out);
}

// round 9
// speedup vs baseline: 3.7203x; 1.5207x over previous
#include <cuda_runtime.h>
#include <cuda_fp16.h>
#include <math.h>
#include <stdint.h>

#define KK 3
#define NN 16384
#define MM 4096
#define DD 128
#define HH 64

// Scratch (device globals: allocation-free rule)
// Features fp16; norms in fp32 from the fp16-ROUNDED values (consistency:
// sq = sn + sm - 2*dot == |x_hat - z_hat|^2, error decays with exp).
__device__ __half g_fxh[KK * NN * HH];
__device__ __half g_fzh[KK * MM * HH];
__device__ float g_sn[KK * NN];
__device__ float g_sm[KK * MM];

__device__ __forceinline__ float sp(float v) {
    return fmaxf(v, 0.0f) + log1pf(__expf(-fabsf(v)));
}

// ======================= async / mma helpers (sm_80 PTX only) =======================
__device__ __forceinline__ uint32_t smem_u32_of(const void* p) {
    return (uint32_t)__cvta_generic_to_shared(p);
}
__device__ __forceinline__ void cp16(uint32_t dst, const void* src) {
    asm volatile("cp.async.cg.shared.global [%0], [%1], 16;" :: "r"(dst), "l"(src));
}
__device__ __forceinline__ void cp_commit() {
    asm volatile("cp.async.commit_group;" ::: "memory");
}
template <int N_>
__device__ __forceinline__ void cp_wait() {
    asm volatile("cp.async.wait_group %0;" :: "n"(N_) : "memory");
}
__device__ __forceinline__ void ldsm4(uint32_t* f, uint32_t addr) {
    asm volatile("ldmatrix.sync.aligned.m8n8.x4.shared.b16 {%0,%1,%2,%3}, [%4];"
                 : "=r"(f[0]), "=r"(f[1]), "=r"(f[2]), "=r"(f[3]) : "r"(addr));
}
__device__ __forceinline__ void mma_f16(float* c, const uint32_t* a, uint32_t b0, uint32_t b1) {
    asm volatile(
        "mma.sync.aligned.m16n8k16.row.col.f32.f16.f16.f32 "
        "{%0,%1,%2,%3}, {%4,%5,%6,%7}, {%8,%9}, {%0,%1,%2,%3};"
        : "+f"(c[0]), "+f"(c[1]), "+f"(c[2]), "+f"(c[3])
        : "r"(a[0]), "r"(a[1]), "r"(a[2]), "r"(a[3]), "r"(b0), "r"(b1));
}
__device__ __forceinline__ void st32(uint32_t addr, uint32_t v) {
    asm volatile("st.shared.u32 [%0], %1;" :: "r"(addr), "r"(v) : "memory");
}
__device__ __forceinline__ uint32_t packh2(__half a, __half b) {
    __half2 p = __halves2half2(a, b);
    return *(uint32_t*)&p;
}

// =====================================================================
// Kernel A: phi MLP on tensor cores.
// CTA: 256 thr / 8 warps, 128 rows; per warp 16 rows x all 64 outs.
// Each GEMM uses fp16 3-way hi/lo split: A:[ah,ah,al], B:[wh,wl,wh],
// K=192 (GEMM1 runs twice, one 64-d half per pass). Row = 384B, 24 chunks,
// XOR-(row&7) swizzle on 16B chunks (same scheme as pair_kernel).
// =====================================================================
#define PRB   384                       // bytes per smem row (192 halves)
#define ABUF_OFF 0
#define ABUF_B  (128 * PRB)             // 49152
#define BBUF_OFF ABUF_B
#define BBUF_B  (64 * PRB)              // 24576
#define BIAS_OFF (ABUF_B + BBUF_B)      // 73728
#define SMEM_PHI (BIAS_OFF + 768)       // 74496

// activation split store: hh@c, hh@c+64, ll@c+128   (c even)
__device__ __forceinline__ void split_st_A(uint32_t base, int row, int c,
                                           float v0, float v1) {
    __half h0 = __float2half(v0), h1 = __float2half(v1);
    __half l0 = __float2half(v0 - __half2float(h0));
    __half l1 = __float2half(v1 - __half2float(h1));
    uint32_t hp = packh2(h0, h1), lp = packh2(l0, l1);
    int r7 = row & 7;
    uint32_t rb = base + (uint32_t)(row * PRB) + (uint32_t)((c & 7) * 2);
    st32(rb + (uint32_t)((((c >> 3)     ) ^ r7) << 4), hp);
    st32(rb + (uint32_t)((((c >> 3) + 8 ) ^ r7) << 4), hp);
    st32(rb + (uint32_t)((((c >> 3) + 16) ^ r7) << 4), lp);
}
// weight split store: wh@c, wl@c+64, wh@c+128
__device__ __forceinline__ void split_st_W(uint32_t base, int row, int c,
                                           float v0, float v1) {
    __half h0 = __float2half(v0), h1 = __float2half(v1);
    __half l0 = __float2half(v0 - __half2float(h0));
    __half l1 = __float2half(v1 - __half2float(h1));
    uint32_t hp = packh2(h0, h1), lp = packh2(l0, l1);
    int r7 = row & 7;
    uint32_t rb = base + (uint32_t)(row * PRB) + (uint32_t)((c & 7) * 2);
    st32(rb + (uint32_t)((((c >> 3)     ) ^ r7) << 4), hp);
    st32(rb + (uint32_t)((((c >> 3) + 8 ) ^ r7) << 4), lp);
    st32(rb + (uint32_t)((((c >> 3) + 16) ^ r7) << 4), hp);
}

// one K=192 GEMM pass: A rows = warp's 16 rows (a_base pre-offset), B 64 rows
__device__ __forceinline__ void gemm192(uint32_t a_base, uint32_t b_base,
                                        int lane, float (&acc)[8][4]) {
    const int a_row = lane & 15;
    const int a_cb  = lane >> 4;
    const int b_row = ((lane >> 4) << 3) + (lane & 7);
    const int b_cb  = (lane >> 3) & 1;
    const int a_r7  = a_row & 7;
    #pragma unroll
    for (int ks = 0; ks < 12; ks++) {
        uint32_t af[4];
        ldsm4(af, a_base + (uint32_t)(a_row * PRB)
                  + (uint32_t)((((2 * ks + a_cb) ^ a_r7)) << 4));
        uint32_t bf[4][4];
        #pragma unroll
        for (int nj2 = 0; nj2 < 4; nj2++) {
            int row = nj2 * 16 + b_row;
            ldsm4(bf[nj2], b_base + (uint32_t)(row * PRB)
                      + (uint32_t)((((2 * ks + b_cb) ^ (row & 7))) << 4));
        }
        #pragma unroll
        for (int nj2 = 0; nj2 < 4; nj2++) {
            mma_f16(acc[2 * nj2 + 0], af, bf[nj2][0], bf[nj2][1]);
            mma_f16(acc[2 * nj2 + 1], af, bf[nj2][2], bf[nj2][3]);
        }
    }
}

__global__ __launch_bounds__(256, 2) void phi_tc(
    const float* __restrict__ x, const float* __restrict__ z,
    const float* __restrict__ W1, const float* __restrict__ b1,
    const float* __restrict__ W2, const float* __restrict__ b2,
    const float* __restrict__ W3, const float* __restrict__ b3) {
    extern __shared__ char sm8[];
    const uint32_t sb = smem_u32_of(sm8);
    const uint32_t aB = sb + ABUF_OFF;
    const uint32_t bB = sb + BBUF_OFF;
    float* biasS = (float*)(sm8 + BIAS_OFF);

    const int t = threadIdx.x;
    const int w = t >> 5, lane = t & 31;
    const int quad = lane >> 2, qid = lane & 3;
    const int k = blockIdx.y;
    const int bx = blockIdx.x;
    const bool isx = (bx < NN / 128);
    const int r0 = (isx ? bx : bx - NN / 128) * 128;
    const float* src = (isx ? x : z) + (size_t)r0 * DD;
    __half* fdst = (isx ? g_fxh + (size_t)k * NN * HH : g_fzh + (size_t)k * MM * HH)
                   + (size_t)r0 * HH;
    float* sdst = (isx ? g_sn + k * NN : g_sm + k * MM) + r0;

    const float* W1k = W1 + k * HH * DD;
    const float* W2k = W2 + k * HH * HH;
    const float* W3k = W3 + k * HH * HH;

    // bias to smem
    if (t < 64)        biasS[t]       = b1[k * HH + t];
    else if (t < 128)  biasS[t]       = b2[k * HH + (t - 64)];
    else if (t < 192)  biasS[t]       = b3[k * HH + (t - 128)];

    const uint32_t aBw = aB + (uint32_t)(w * 16 * PRB);

    float acc[8][4];
    #pragma unroll
    for (int nj = 0; nj < 8; nj++)
        #pragma unroll
        for (int r = 0; r < 4; r++) acc[nj][r] = 0.0f;

    // ---- GEMM1: two 64-d halves ----
    #pragma unroll
    for (int half = 0; half < 2; half++) {
        if (half == 1) __syncthreads();   // prior mma reads done before overwrite
        // x tile: 128 rows x 64 d -> split into A buf
        #pragma unroll
        for (int i = 0; i < 8; i++) {
            int q = t + i * 256;
            int row = q >> 4, c = (q & 15) << 2;
            float4 v = *(const float4*)(src + (size_t)row * DD + half * 64 + c);
            split_st_A(aB, row, c, v.x, v.y);
            split_st_A(aB, row, c + 2, v.z, v.w);
        }
        // W1 half: 64 rows x 64 d -> split into B buf
        #pragma unroll
        for (int i = 0; i < 4; i++) {
            int q = t + i * 256;
            int row = q >> 4, c = (q & 15) << 2;
            float4 v = *(const float4*)(W1k + (size_t)row * DD + half * 64 + c);
            split_st_W(bB, row, c, v.x, v.y);
            split_st_W(bB, row, c + 2, v.z, v.w);
        }
        __syncthreads();
        gemm192(aBw, bB, lane, acc);
    }
    __syncthreads();

    // ---- layer1 epilogue -> A buf; W2 -> B buf ----
    #pragma unroll
    for (int nj = 0; nj < 8; nj++) {
        int col = nj * 8 + 2 * qid;
        float v0 = sp(acc[nj][0] + biasS[col]);
        float v1 = sp(acc[nj][1] + biasS[col + 1]);
        float v2 = sp(acc[nj][2] + biasS[col]);
        float v3 = sp(acc[nj][3] + biasS[col + 1]);
        split_st_A(aB, w * 16 + quad, col, v0, v1);
        split_st_A(aB, w * 16 + quad + 8, col, v2, v3);
    }
    #pragma unroll
    for (int i = 0; i < 4; i++) {
        int q = t + i * 256;
        int row = q >> 4, c = (q & 15) << 2;
        float4 v = *(const float4*)(W2k + (size_t)row * HH + c);
        split_st_W(bB, row, c, v.x, v.y);
        split_st_W(bB, row, c + 2, v.z, v.w);
    }
    __syncthreads();

    #pragma unroll
    for (int nj = 0; nj < 8; nj++)
        #pragma unroll
        for (int r = 0; r < 4; r++) acc[nj][r] = 0.0f;
    gemm192(aBw, bB, lane, acc);
    __syncthreads();

    // ---- layer2 epilogue -> A buf; W3 -> B buf ----
    #pragma unroll
    for (int nj = 0; nj < 8; nj++) {
        int col = nj * 8 + 2 * qid;
        float v0 = sp(acc[nj][0] + biasS[64 + col]);
        float v1 = sp(acc[nj][1] + biasS[64 + col + 1]);
        float v2 = sp(acc[nj][2] + biasS[64 + col]);
        float v3 = sp(acc[nj][3] + biasS[64 + col + 1]);
        split_st_A(aB, w * 16 + quad, col, v0, v1);
        split_st_A(aB, w * 16 + quad + 8, col, v2, v3);
    }
    #pragma unroll
    for (int i = 0; i < 4; i++) {
        int q = t + i * 256;
        int row = q >> 4, c = (q & 15) << 2;
        float4 v = *(const float4*)(W3k + (size_t)row * HH + c);
        split_st_W(bB, row, c, v.x, v.y);
        split_st_W(bB, row, c + 2, v.z, v.w);
    }
    __syncthreads();

    #pragma unroll
    for (int nj = 0; nj < 8; nj++)
        #pragma unroll
        for (int r = 0; r < 4; r++) acc[nj][r] = 0.0f;
    gemm192(aBw, bB, lane, acc);

    // ---- final: features (fp16) + fp32 norms of ROUNDED values ----
    float s0 = 0.0f, s1 = 0.0f;
    #pragma unroll
    for (int nj = 0; nj < 8; nj++) {
        int col = nj * 8 + 2 * qid;
        float f0 = acc[nj][0] + biasS[128 + col];
        float f1 = acc[nj][1] + biasS[128 + col + 1];
        float f2 = acc[nj][2] + biasS[128 + col];
        float f3 = acc[nj][3] + biasS[128 + col + 1];
        __half h0 = __float2half(f0), h1 = __float2half(f1);
        __half h2 = __float2half(f2), h3 = __float2half(f3);
        int row0 = w * 16 + quad, row1 = row0 + 8;
        *(uint32_t*)((char*)fdst + ((size_t)row0 * HH + col) * 2) = packh2(h0, h1);
        *(uint32_t*)((char*)fdst + ((size_t)row1 * HH + col) * 2) = packh2(h2, h3);
        float r00 = __half2float(h0), r01 = __half2float(h1);
        float r10 = __half2float(h2), r11 = __half2float(h3);
        s0 += r00 * r00 + r01 * r01;
        s1 += r10 * r10 + r11 * r11;
    }
    s0 += __shfl_xor_sync(0xffffffffu, s0, 1);
    s0 += __shfl_xor_sync(0xffffffffu, s0, 2);
    s1 += __shfl_xor_sync(0xffffffffu, s1, 1);
    s1 += __shfl_xor_sync(0xffffffffu, s1, 2);
    if (qid == 0) {
        sdst[w * 16 + quad] = s0;
        sdst[w * 16 + quad + 8] = s1;
    }
}

// =====================================================================
// Kernel B: mma.sync fp16 pairwise GEMM + fused RBF epilogue (unchanged r8).
// =====================================================================
#define NT 128
#define MT 64
#define A_STB (128 * 128)
#define B_STB (64 * 128)
#define STG_B (A_STB + B_STB)
#define OFF_SN2 0
#define OFF_SM2 1536
#define OFF_ST2 2304
#define SMEM_TOT2 (OFF_ST2 + 3 * STG_B)   // 76032

__device__ __forceinline__ void load_chunk(int k, int n0, int m0,
                                           uint32_t stage, int t) {
    const __half* gA = g_fxh + ((size_t)k * NN + n0) * HH;
    const __half* gB = g_fzh + ((size_t)k * MM + m0) * HH;
    #pragma unroll
    for (int i = 0; i < 4; i++) {
        int q = t + i * 256;
        int r = q >> 3, cc = q & 7;
        cp16(stage + r * 128 + (uint32_t)((cc ^ (r & 7)) << 4),
             (const char*)(gA + (size_t)r * HH) + cc * 16);
    }
    #pragma unroll
    for (int i = 0; i < 2; i++) {
        int q = t + i * 256;
        int r = q >> 3, cc = q & 7;
        cp16(stage + A_STB + r * 128 + (uint32_t)((cc ^ (r & 7)) << 4),
             (const char*)(gB + (size_t)r * HH) + cc * 16);
    }
}

__global__ __launch_bounds__(256, 2) void pair_kernel(
    const float* __restrict__ log_sigma, const float* __restrict__ kw,
    float* __restrict__ out) {
    extern __shared__ char sm8[];
    const uint32_t sb = smem_u32_of(sm8);
    float* snS = (float*)(sm8 + OFF_SN2);
    float* smS = (float*)(sm8 + OFF_SM2);

    const int t = threadIdx.x;
    const int w = t >> 5, lane = t & 31;
    const int quad = lane >> 2, qid = lane & 3;
    const int wn = w & 3, wm = w >> 2;
    const int nb = wn * 32, mb = wm * 32;
    const int m0 = blockIdx.x * MT;
    const int n0 = blockIdx.y * NT;

    load_chunk(0, n0, m0, sb + OFF_ST2 + 0 * STG_B, t); cp_commit();
    load_chunk(1, n0, m0, sb + OFF_ST2 + 1 * STG_B, t); cp_commit();
    load_chunk(2, n0, m0, sb + OFF_ST2 + 2 * STG_B, t); cp_commit();

    for (int q = t; q < 3 * 128; q += 256)
        snS[q] = g_sn[(q >> 7) * NN + n0 + (q & 127)];
    for (int q = t; q < 3 * 64; q += 256)
        smS[q] = g_sm[(q >> 6) * MM + m0 + (q & 63)];

    float w0r = kw[0], w1r = kw[1], w2r = kw[2];
    float wmax = fmaxf(fmaxf(w0r, w1r), w2r);
    float ew0 = __expf(w0r - wmax), ew1 = __expf(w1r - wmax), ew2 = __expf(w2r - wmax);
    float winv = 1.0f / (ew0 + ew1 + ew2);
    float wkv[3] = {ew0 * winv, ew1 * winv, ew2 * winv};
    float c1[3];
    #pragma unroll
    for (int k = 0; k < 3; k++)
        c1[k] = 0.5f * exp2f(-log_sigma[k] * 3.3219280948873623f);

    float res[2][4][4];
    #pragma unroll
    for (int mi = 0; mi < 2; mi++)
        #pragma unroll
        for (int nj = 0; nj < 4; nj++)
            #pragma unroll
            for (int r = 0; r < 4; r++) res[mi][nj][r] = 0.0f;

    const int a_row = nb + (lane & 15);
    const int a_cb  = lane >> 4;
    const int b_row = mb + ((lane >> 4) << 3) + (lane & 7);
    const int b_cb  = (lane >> 3) & 1;
    const uint32_t a_r7x = (uint32_t)((a_row & 7) << 4);
    const uint32_t b_r7x = (uint32_t)((b_row & 7) << 4);
    uint32_t aoff[4], boff[4];
    #pragma unroll
    for (int ks = 0; ks < 4; ks++) {
        aoff[ks] = (uint32_t)(a_row * 128) + ((uint32_t)((2 * ks + a_cb) << 4) ^ a_r7x);
        boff[ks] = (uint32_t)(b_row * 128) + ((uint32_t)((2 * ks + b_cb) << 4) ^ b_r7x);
    }

    #pragma unroll
    for (int k = 0; k < KK; k++) {
        if (k == 0)      cp_wait<2>();
        else if (k == 1) cp_wait<1>();
        else             cp_wait<0>();
        __syncthreads();

        const uint32_t a_base = sb + OFF_ST2 + (uint32_t)k * STG_B;
        const uint32_t b_base = a_base + A_STB;

        float acc[2][4][4];
        #pragma unroll
        for (int mi = 0; mi < 2; mi++)
            #pragma unroll
            for (int nj = 0; nj < 4; nj++)
                #pragma unroll
                for (int r = 0; r < 4; r++) acc[mi][nj][r] = 0.0f;

        uint32_t af[2][2][4], bf[2][2][4];
        ldsm4(af[0][0], a_base + aoff[0]);
        ldsm4(af[0][1], a_base + aoff[0] + 16 * 128);
        ldsm4(bf[0][0], b_base + boff[0]);
        ldsm4(bf[0][1], b_base + boff[0] + 16 * 128);

        #pragma unroll
        for (int ks = 0; ks < 4; ks++) {
            int cur = ks & 1, nxt = cur ^ 1;
            if (ks < 3) {
                ldsm4(af[nxt][0], a_base + aoff[ks + 1]);
                ldsm4(af[nxt][1], a_base + aoff[ks + 1] + 16 * 128);
                ldsm4(bf[nxt][0], b_base + boff[ks + 1]);
                ldsm4(bf[nxt][1], b_base + boff[ks + 1] + 16 * 128);
            }
            #pragma unroll
            for (int mi = 0; mi < 2; mi++)
                #pragma unroll
                for (int nj2 = 0; nj2 < 2; nj2++) {
                    mma_f16(acc[mi][2 * nj2 + 0], af[cur][mi], bf[cur][nj2][0], bf[cur][nj2][1]);
                    mma_f16(acc[mi][2 * nj2 + 1], af[cur][mi], bf[cur][nj2][2], bf[cur][nj2][3]);
                }
        }

        {
            float c1k = c1[k], c2k = 2.0f * c1k, wkk = wkv[k];
            float pn[2][2];
            #pragma unroll
            for (int mi = 0; mi < 2; mi++) {
                pn[mi][0] = c1k * snS[k * 128 + nb + mi * 16 + quad];
                pn[mi][1] = c1k * snS[k * 128 + nb + mi * 16 + quad + 8];
            }
            #pragma unroll
            for (int nj = 0; nj < 4; nj++) {
                float2 pm2 = *(float2*)&smS[k * 64 + mb + nj * 8 + 2 * qid];
                float pm0 = c1k * pm2.x, pm1 = c1k * pm2.y;
                #pragma unroll
                for (int mi = 0; mi < 2; mi++) {
                    float g0 = fminf(fmaf(c2k, acc[mi][nj][0], -(pn[mi][0] + pm0)), 0.0f);
                    float g1 = fminf(fmaf(c2k, acc[mi][nj][1], -(pn[mi][0] + pm1)), 0.0f);
                    float g2 = fminf(fmaf(c2k, acc[mi][nj][2], -(pn[mi][1] + pm0)), 0.0f);
                    float g3 = fminf(fmaf(c2k, acc[mi][nj][3], -(pn[mi][1] + pm1)), 0.0f);
                    res[mi][nj][0] = fmaf(wkk, __expf(g0), res[mi][nj][0]);
                    res[mi][nj][1] = fmaf(wkk, __expf(g1), res[mi][nj][1]);
                    res[mi][nj][2] = fmaf(wkk, __expf(g2), res[mi][nj][2]);
                    res[mi][nj][3] = fmaf(wkk, __expf(g3), res[mi][nj][3]);
                }
            }
        }
    }

    #pragma unroll
    for (int mi = 0; mi < 2; mi++) {
        int nrow = n0 + nb + mi * 16 + quad;
        #pragma unroll
        for (int nj = 0; nj < 4; nj++) {
            float* p0 = out + (size_t)nrow * MM + m0 + mb + nj * 8 + 2 * qid;
            *(float2*)p0 = make_float2(res[mi][nj][0], res[mi][nj][1]);
            float* p1 = p0 + (size_t)8 * MM;
            *(float2*)p1 = make_float2(res[mi][nj][2], res[mi][nj][3]);
        }
    }
}

extern "C" void kernel_launch(void* const* d_in, const int* in_sizes, int n_in,
                              void* d_out, int out_size) {
    const float* x  = (const float*)d_in[0];
    const float* z  = (const float*)d_in[1];
    const float* W1 = (const float*)d_in[2];
    const float* b1 = (const float*)d_in[3];
    const float* W2 = (const float*)d_in[4];
    const float* b2 = (const float*)d_in[5];
    const float* W3 = (const float*)d_in[6];
    const float* b3 = (const float*)d_in[7];
    const float* ls = (const float*)d_in[8];
    const float* kwp = (const float*)d_in[9];
    float* out = (float*)d_out;

    cudaFuncSetAttribute(phi_tc, cudaFuncAttributeMaxDynamicSharedMemorySize, SMEM_PHI);
    cudaFuncSetAttribute(pair_kernel, cudaFuncAttributeMaxDynamicSharedMemorySize, SMEM_TOT2);

    phi_tc<<<dim3((NN + MM) / 128, 3), 256, SMEM_PHI>>>(x, z, W1, b1, W2, b2, W3, b3);
    pair_kernel<<<dim3(MM / MT, NN / NT), 256, SMEM_TOT2>>>(ls, kwp, out);
}

// round 10
// speedup vs baseline: 3.7828x; 1.0168x over previous
#include <cuda_runtime.h>
#include <cuda_fp16.h>
#include <math.h>
#include <stdint.h>

#define KK 3
#define NN 16384
#define MM 4096
#define DD 128
#define HH 64

// Scratch (device globals: allocation-free rule)
// Features fp16; norms in fp32 from the fp16-ROUNDED values (consistency:
// sq = sn + sm - 2*dot == |x_hat - z_hat|^2, error decays with exp).
__device__ __half g_fxh[KK * NN * HH];
__device__ __half g_fzh[KK * MM * HH];
__device__ float g_sn[KK * NN];
__device__ float g_sm[KK * MM];

__device__ __forceinline__ float sp(float v) {
    return fmaxf(v, 0.0f) + log1pf(__expf(-fabsf(v)));
}

// ======================= async / mma helpers (sm_80 PTX only) =======================
__device__ __forceinline__ uint32_t smem_u32_of(const void* p) {
    return (uint32_t)__cvta_generic_to_shared(p);
}
__device__ __forceinline__ void cp16(uint32_t dst, const void* src) {
    asm volatile("cp.async.cg.shared.global [%0], [%1], 16;" :: "r"(dst), "l"(src));
}
__device__ __forceinline__ void cp_commit() {
    asm volatile("cp.async.commit_group;" ::: "memory");
}
template <int N_>
__device__ __forceinline__ void cp_wait() {
    asm volatile("cp.async.wait_group %0;" :: "n"(N_) : "memory");
}
__device__ __forceinline__ void ldsm4(uint32_t* f, uint32_t addr) {
    asm volatile("ldmatrix.sync.aligned.m8n8.x4.shared.b16 {%0,%1,%2,%3}, [%4];"
                 : "=r"(f[0]), "=r"(f[1]), "=r"(f[2]), "=r"(f[3]) : "r"(addr));
}
__device__ __forceinline__ void mma_f16(float* c, const uint32_t* a, uint32_t b0, uint32_t b1) {
    asm volatile(
        "mma.sync.aligned.m16n8k16.row.col.f32.f16.f16.f32 "
        "{%0,%1,%2,%3}, {%4,%5,%6,%7}, {%8,%9}, {%0,%1,%2,%3};"
        : "+f"(c[0]), "+f"(c[1]), "+f"(c[2]), "+f"(c[3])
        : "r"(a[0]), "r"(a[1]), "r"(a[2]), "r"(a[3]), "r"(b0), "r"(b1));
}
__device__ __forceinline__ void st32(uint32_t addr, uint32_t v) {
    asm volatile("st.shared.u32 [%0], %1;" :: "r"(addr), "r"(v) : "memory");
}
__device__ __forceinline__ uint32_t packh2(__half a, __half b) {
    __half2 p = __halves2half2(a, b);
    return *(uint32_t*)&p;
}

// =====================================================================
// Kernel A: phi MLP on tensor cores (unchanged from r9).
// =====================================================================
#define PRB   384
#define ABUF_OFF 0
#define ABUF_B  (128 * PRB)
#define BBUF_OFF ABUF_B
#define BBUF_B  (64 * PRB)
#define BIAS_OFF (ABUF_B + BBUF_B)
#define SMEM_PHI (BIAS_OFF + 768)

__device__ __forceinline__ void split_st_A(uint32_t base, int row, int c,
                                           float v0, float v1) {
    __half h0 = __float2half(v0), h1 = __float2half(v1);
    __half l0 = __float2half(v0 - __half2float(h0));
    __half l1 = __float2half(v1 - __half2float(h1));
    uint32_t hp = packh2(h0, h1), lp = packh2(l0, l1);
    int r7 = row & 7;
    uint32_t rb = base + (uint32_t)(row * PRB) + (uint32_t)((c & 7) * 2);
    st32(rb + (uint32_t)((((c >> 3)     ) ^ r7) << 4), hp);
    st32(rb + (uint32_t)((((c >> 3) + 8 ) ^ r7) << 4), hp);
    st32(rb + (uint32_t)((((c >> 3) + 16) ^ r7) << 4), lp);
}
__device__ __forceinline__ void split_st_W(uint32_t base, int row, int c,
                                           float v0, float v1) {
    __half h0 = __float2half(v0), h1 = __float2half(v1);
    __half l0 = __float2half(v0 - __half2float(h0));
    __half l1 = __float2half(v1 - __half2float(h1));
    uint32_t hp = packh2(h0, h1), lp = packh2(l0, l1);
    int r7 = row & 7;
    uint32_t rb = base + (uint32_t)(row * PRB) + (uint32_t)((c & 7) * 2);
    st32(rb + (uint32_t)((((c >> 3)     ) ^ r7) << 4), hp);
    st32(rb + (uint32_t)((((c >> 3) + 8 ) ^ r7) << 4), lp);
    st32(rb + (uint32_t)((((c >> 3) + 16) ^ r7) << 4), hp);
}

__device__ __forceinline__ void gemm192(uint32_t a_base, uint32_t b_base,
                                        int lane, float (&acc)[8][4]) {
    const int a_row = lane & 15;
    const int a_cb  = lane >> 4;
    const int b_row = ((lane >> 4) << 3) + (lane & 7);
    const int b_cb  = (lane >> 3) & 1;
    const int a_r7  = a_row & 7;
    #pragma unroll
    for (int ks = 0; ks < 12; ks++) {
        uint32_t af[4];
        ldsm4(af, a_base + (uint32_t)(a_row * PRB)
                  + (uint32_t)((((2 * ks + a_cb) ^ a_r7)) << 4));
        uint32_t bf[4][4];
        #pragma unroll
        for (int nj2 = 0; nj2 < 4; nj2++) {
            int row = nj2 * 16 + b_row;
            ldsm4(bf[nj2], b_base + (uint32_t)(row * PRB)
                      + (uint32_t)((((2 * ks + b_cb) ^ (row & 7))) << 4));
        }
        #pragma unroll
        for (int nj2 = 0; nj2 < 4; nj2++) {
            mma_f16(acc[2 * nj2 + 0], af, bf[nj2][0], bf[nj2][1]);
            mma_f16(acc[2 * nj2 + 1], af, bf[nj2][2], bf[nj2][3]);
        }
    }
}

__global__ __launch_bounds__(256, 2) void phi_tc(
    const float* __restrict__ x, const float* __restrict__ z,
    const float* __restrict__ W1, const float* __restrict__ b1,
    const float* __restrict__ W2, const float* __restrict__ b2,
    const float* __restrict__ W3, const float* __restrict__ b3) {
    extern __shared__ char sm8[];
    const uint32_t sb = smem_u32_of(sm8);
    const uint32_t aB = sb + ABUF_OFF;
    const uint32_t bB = sb + BBUF_OFF;
    float* biasS = (float*)(sm8 + BIAS_OFF);

    const int t = threadIdx.x;
    const int w = t >> 5, lane = t & 31;
    const int quad = lane >> 2, qid = lane & 3;
    const int k = blockIdx.y;
    const int bx = blockIdx.x;
    const bool isx = (bx < NN / 128);
    const int r0 = (isx ? bx : bx - NN / 128) * 128;
    const float* src = (isx ? x : z) + (size_t)r0 * DD;
    __half* fdst = (isx ? g_fxh + (size_t)k * NN * HH : g_fzh + (size_t)k * MM * HH)
                   + (size_t)r0 * HH;
    float* sdst = (isx ? g_sn + k * NN : g_sm + k * MM) + r0;

    const float* W1k = W1 + k * HH * DD;
    const float* W2k = W2 + k * HH * HH;
    const float* W3k = W3 + k * HH * HH;

    if (t < 64)        biasS[t]       = b1[k * HH + t];
    else if (t < 128)  biasS[t]       = b2[k * HH + (t - 64)];
    else if (t < 192)  biasS[t]       = b3[k * HH + (t - 128)];

    const uint32_t aBw = aB + (uint32_t)(w * 16 * PRB);

    float acc[8][4];
    #pragma unroll
    for (int nj = 0; nj < 8; nj++)
        #pragma unroll
        for (int r = 0; r < 4; r++) acc[nj][r] = 0.0f;

    #pragma unroll
    for (int half = 0; half < 2; half++) {
        if (half == 1) __syncthreads();
        #pragma unroll
        for (int i = 0; i < 8; i++) {
            int q = t + i * 256;
            int row = q >> 4, c = (q & 15) << 2;
            float4 v = *(const float4*)(src + (size_t)row * DD + half * 64 + c);
            split_st_A(aB, row, c, v.x, v.y);
            split_st_A(aB, row, c + 2, v.z, v.w);
        }
        #pragma unroll
        for (int i = 0; i < 4; i++) {
            int q = t + i * 256;
            int row = q >> 4, c = (q & 15) << 2;
            float4 v = *(const float4*)(W1k + (size_t)row * DD + half * 64 + c);
            split_st_W(bB, row, c, v.x, v.y);
            split_st_W(bB, row, c + 2, v.z, v.w);
        }
        __syncthreads();
        gemm192(aBw, bB, lane, acc);
    }
    __syncthreads();

    #pragma unroll
    for (int nj = 0; nj < 8; nj++) {
        int col = nj * 8 + 2 * qid;
        float v0 = sp(acc[nj][0] + biasS[col]);
        float v1 = sp(acc[nj][1] + biasS[col + 1]);
        float v2 = sp(acc[nj][2] + biasS[col]);
        float v3 = sp(acc[nj][3] + biasS[col + 1]);
        split_st_A(aB, w * 16 + quad, col, v0, v1);
        split_st_A(aB, w * 16 + quad + 8, col, v2, v3);
    }
    #pragma unroll
    for (int i = 0; i < 4; i++) {
        int q = t + i * 256;
        int row = q >> 4, c = (q & 15) << 2;
        float4 v = *(const float4*)(W2k + (size_t)row * HH + c);
        split_st_W(bB, row, c, v.x, v.y);
        split_st_W(bB, row, c + 2, v.z, v.w);
    }
    __syncthreads();

    #pragma unroll
    for (int nj = 0; nj < 8; nj++)
        #pragma unroll
        for (int r = 0; r < 4; r++) acc[nj][r] = 0.0f;
    gemm192(aBw, bB, lane, acc);
    __syncthreads();

    #pragma unroll
    for (int nj = 0; nj < 8; nj++) {
        int col = nj * 8 + 2 * qid;
        float v0 = sp(acc[nj][0] + biasS[64 + col]);
        float v1 = sp(acc[nj][1] + biasS[64 + col + 1]);
        float v2 = sp(acc[nj][2] + biasS[64 + col]);
        float v3 = sp(acc[nj][3] + biasS[64 + col + 1]);
        split_st_A(aB, w * 16 + quad, col, v0, v1);
        split_st_A(aB, w * 16 + quad + 8, col, v2, v3);
    }
    #pragma unroll
    for (int i = 0; i < 4; i++) {
        int q = t + i * 256;
        int row = q >> 4, c = (q & 15) << 2;
        float4 v = *(const float4*)(W3k + (size_t)row * HH + c);
        split_st_W(bB, row, c, v.x, v.y);
        split_st_W(bB, row, c + 2, v.z, v.w);
    }
    __syncthreads();

    #pragma unroll
    for (int nj = 0; nj < 8; nj++)
        #pragma unroll
        for (int r = 0; r < 4; r++) acc[nj][r] = 0.0f;
    gemm192(aBw, bB, lane, acc);

    float s0 = 0.0f, s1 = 0.0f;
    #pragma unroll
    for (int nj = 0; nj < 8; nj++) {
        int col = nj * 8 + 2 * qid;
        float f0 = acc[nj][0] + biasS[128 + col];
        float f1 = acc[nj][1] + biasS[128 + col + 1];
        float f2 = acc[nj][2] + biasS[128 + col];
        float f3 = acc[nj][3] + biasS[128 + col + 1];
        __half h0 = __float2half(f0), h1 = __float2half(f1);
        __half h2 = __float2half(f2), h3 = __float2half(f3);
        int row0 = w * 16 + quad, row1 = row0 + 8;
        *(uint32_t*)((char*)fdst + ((size_t)row0 * HH + col) * 2) = packh2(h0, h1);
        *(uint32_t*)((char*)fdst + ((size_t)row1 * HH + col) * 2) = packh2(h2, h3);
        float r00 = __half2float(h0), r01 = __half2float(h1);
        float r10 = __half2float(h2), r11 = __half2float(h3);
        s0 += r00 * r00 + r01 * r01;
        s1 += r10 * r10 + r11 * r11;
    }
    s0 += __shfl_xor_sync(0xffffffffu, s0, 1);
    s0 += __shfl_xor_sync(0xffffffffu, s0, 2);
    s1 += __shfl_xor_sync(0xffffffffu, s1, 1);
    s1 += __shfl_xor_sync(0xffffffffu, s1, 2);
    if (qid == 0) {
        sdst[w * 16 + quad] = s0;
        sdst[w * 16 + quad + 8] = s1;
    }
}

// =====================================================================
// Kernel B: mma.sync fp16 pairwise GEMM + fused RBF epilogue.
// r10: all 3 chunks prefetched; ONE wait + ONE barrier, then barrier-free
// k-loop (warps desync; epilogue EX2 overlaps other warps' LDSM/MMA).
// Epilogue: exp2-folded constants, no clamp -> fma + EX2 + fma per element.
// =====================================================================
#define NT 128
#define MT 64
#define A_STB (128 * 128)
#define B_STB (64 * 128)
#define STG_B (A_STB + B_STB)
#define OFF_SN2 0
#define OFF_SM2 1536
#define OFF_ST2 2304
#define SMEM_TOT2 (OFF_ST2 + 3 * STG_B)   // 76032

__device__ __forceinline__ void load_chunk(int k, int n0, int m0,
                                           uint32_t stage, int t) {
    const __half* gA = g_fxh + ((size_t)k * NN + n0) * HH;
    const __half* gB = g_fzh + ((size_t)k * MM + m0) * HH;
    #pragma unroll
    for (int i = 0; i < 4; i++) {
        int q = t + i * 256;
        int r = q >> 3, cc = q & 7;
        cp16(stage + r * 128 + (uint32_t)((cc ^ (r & 7)) << 4),
             (const char*)(gA + (size_t)r * HH) + cc * 16);
    }
    #pragma unroll
    for (int i = 0; i < 2; i++) {
        int q = t + i * 256;
        int r = q >> 3, cc = q & 7;
        cp16(stage + A_STB + r * 128 + (uint32_t)((cc ^ (r & 7)) << 4),
             (const char*)(gB + (size_t)r * HH) + cc * 16);
    }
}

__global__ __launch_bounds__(256, 2) void pair_kernel(
    const float* __restrict__ log_sigma, const float* __restrict__ kw,
    float* __restrict__ out) {
    extern __shared__ char sm8[];
    const uint32_t sb = smem_u32_of(sm8);
    float* snS = (float*)(sm8 + OFF_SN2);
    float* smS = (float*)(sm8 + OFF_SM2);

    const int t = threadIdx.x;
    const int w = t >> 5, lane = t & 31;
    const int quad = lane >> 2, qid = lane & 3;
    const int wn = w & 3, wm = w >> 2;
    const int nb = wn * 32, mb = wm * 32;
    const int m0 = blockIdx.x * MT;
    const int n0 = blockIdx.y * NT;

    load_chunk(0, n0, m0, sb + OFF_ST2 + 0 * STG_B, t);
    load_chunk(1, n0, m0, sb + OFF_ST2 + 1 * STG_B, t);
    load_chunk(2, n0, m0, sb + OFF_ST2 + 2 * STG_B, t);
    cp_commit();

    for (int q = t; q < 3 * 128; q += 256)
        snS[q] = g_sn[(q >> 7) * NN + n0 + (q & 127)];
    for (int q = t; q < 3 * 64; q += 256)
        smS[q] = g_sm[(q >> 6) * MM + m0 + (q & 63)];

    float w0r = kw[0], w1r = kw[1], w2r = kw[2];
    float wmax = fmaxf(fmaxf(w0r, w1r), w2r);
    float ew0 = __expf(w0r - wmax), ew1 = __expf(w1r - wmax), ew2 = __expf(w2r - wmax);
    float winv = 1.0f / (ew0 + ew1 + ew2);
    float wkv[3] = {ew0 * winv, ew1 * winv, ew2 * winv};
    // l[k] = log2(e) / (2*10^ls): kxz = exp2(-l*(sn+sm) + 2l*dot)
    float lk[3];
    #pragma unroll
    for (int k = 0; k < 3; k++)
        lk[k] = 0.72134752044448170f * exp2f(-log_sigma[k] * 3.3219280948873623f);

    float res[2][4][4];
    #pragma unroll
    for (int mi = 0; mi < 2; mi++)
        #pragma unroll
        for (int nj = 0; nj < 4; nj++)
            #pragma unroll
            for (int r = 0; r < 4; r++) res[mi][nj][r] = 0.0f;

    const int a_row = nb + (lane & 15);
    const int a_cb  = lane >> 4;
    const int b_row = mb + ((lane >> 4) << 3) + (lane & 7);
    const int b_cb  = (lane >> 3) & 1;
    const uint32_t a_r7x = (uint32_t)((a_row & 7) << 4);
    const uint32_t b_r7x = (uint32_t)((b_row & 7) << 4);
    uint32_t aoff[4], boff[4];
    #pragma unroll
    for (int ks = 0; ks < 4; ks++) {
        aoff[ks] = (uint32_t)(a_row * 128) + ((uint32_t)((2 * ks + a_cb) << 4) ^ a_r7x);
        boff[ks] = (uint32_t)(b_row * 128) + ((uint32_t)((2 * ks + b_cb) << 4) ^ b_r7x);
    }

    // single wait + barrier; everything after is barrier-free
    cp_wait<0>();
    __syncthreads();

    #pragma unroll
    for (int k = 0; k < KK; k++) {
        const uint32_t a_base = sb + OFF_ST2 + (uint32_t)k * STG_B;
        const uint32_t b_base = a_base + A_STB;

        float acc[2][4][4];
        #pragma unroll
        for (int mi = 0; mi < 2; mi++)
            #pragma unroll
            for (int nj = 0; nj < 4; nj++)
                #pragma unroll
                for (int r = 0; r < 4; r++) acc[mi][nj][r] = 0.0f;

        uint32_t af[2][2][4], bf[2][2][4];
        ldsm4(af[0][0], a_base + aoff[0]);
        ldsm4(af[0][1], a_base + aoff[0] + 16 * 128);
        ldsm4(bf[0][0], b_base + boff[0]);
        ldsm4(bf[0][1], b_base + boff[0] + 16 * 128);

        #pragma unroll
        for (int ks = 0; ks < 4; ks++) {
            int cur = ks & 1, nxt = cur ^ 1;
            if (ks < 3) {
                ldsm4(af[nxt][0], a_base + aoff[ks + 1]);
                ldsm4(af[nxt][1], a_base + aoff[ks + 1] + 16 * 128);
                ldsm4(bf[nxt][0], b_base + boff[ks + 1]);
                ldsm4(bf[nxt][1], b_base + boff[ks + 1] + 16 * 128);
            }
            #pragma unroll
            for (int mi = 0; mi < 2; mi++)
                #pragma unroll
                for (int nj2 = 0; nj2 < 2; nj2++) {
                    mma_f16(acc[mi][2 * nj2 + 0], af[cur][mi], bf[cur][nj2][0], bf[cur][nj2][1]);
                    mma_f16(acc[mi][2 * nj2 + 1], af[cur][mi], bf[cur][nj2][2], bf[cur][nj2][3]);
                }
        }

        // epilogue: res += wk * exp2(2l*dot - l*(sn+sm)); no clamp needed
        // (consistency trick bounds the exponent above by ~+1e-5)
        {
            float l = lk[k], l2 = 2.0f * l, wkk = wkv[k];
            float pn[2][2];
            #pragma unroll
            for (int mi = 0; mi < 2; mi++) {
                pn[mi][0] = l * snS[k * 128 + nb + mi * 16 + quad];
                pn[mi][1] = l * snS[k * 128 + nb + mi * 16 + quad + 8];
            }
            #pragma unroll
            for (int nj = 0; nj < 4; nj++) {
                float2 pm2 = *(float2*)&smS[k * 64 + mb + nj * 8 + 2 * qid];
                float pm0 = l * pm2.x, pm1 = l * pm2.y;
                #pragma unroll
                for (int mi = 0; mi < 2; mi++) {
                    float p00 = pn[mi][0] + pm0, p01 = pn[mi][0] + pm1;
                    float p10 = pn[mi][1] + pm0, p11 = pn[mi][1] + pm1;
                    float e0 = exp2f(fmaf(l2, acc[mi][nj][0], -p00));
                    float e1 = exp2f(fmaf(l2, acc[mi][nj][1], -p01));
                    float e2 = exp2f(fmaf(l2, acc[mi][nj][2], -p10));
                    float e3 = exp2f(fmaf(l2, acc[mi][nj][3], -p11));
                    res[mi][nj][0] = fmaf(wkk, e0, res[mi][nj][0]);
                    res[mi][nj][1] = fmaf(wkk, e1, res[mi][nj][1]);
                    res[mi][nj][2] = fmaf(wkk, e2, res[mi][nj][2]);
                    res[mi][nj][3] = fmaf(wkk, e3, res[mi][nj][3]);
                }
            }
        }
    }

    #pragma unroll
    for (int mi = 0; mi < 2; mi++) {
        int nrow = n0 + nb + mi * 16 + quad;
        #pragma unroll
        for (int nj = 0; nj < 4; nj++) {
            float* p0 = out + (size_t)nrow * MM + m0 + mb + nj * 8 + 2 * qid;
            *(float2*)p0 = make_float2(res[mi][nj][0], res[mi][nj][1]);
            float* p1 = p0 + (size_t)8 * MM;
            *(float2*)p1 = make_float2(res[mi][nj][2], res[mi][nj][3]);
        }
    }
}

extern "C" void kernel_launch(void* const* d_in, const int* in_sizes, int n_in,
                              void* d_out, int out_size) {
    const float* x  = (const float*)d_in[0];
    const float* z  = (const float*)d_in[1];
    const float* W1 = (const float*)d_in[2];
    const float* b1 = (const float*)d_in[3];
    const float* W2 = (const float*)d_in[4];
    const float* b2 = (const float*)d_in[5];
    const float* W3 = (const float*)d_in[6];
    const float* b3 = (const float*)d_in[7];
    const float* ls = (const float*)d_in[8];
    const float* kwp = (const float*)d_in[9];
    float* out = (float*)d_out;

    cudaFuncSetAttribute(phi_tc, cudaFuncAttributeMaxDynamicSharedMemorySize, SMEM_PHI);
    cudaFuncSetAttribute(pair_kernel, cudaFuncAttributeMaxDynamicSharedMemorySize, SMEM_TOT2);

    phi_tc<<<dim3((NN + MM) / 128, 3), 256, SMEM_PHI>>>(x, z, W1, b1, W2, b2, W3, b3);
    pair_kernel<<<dim3(MM / MT, NN / NT), 256, SMEM_TOT2>>>(ls, kwp, out);
}